// round 1
// baseline (speedup 1.0000x reference)
#include <cuda_runtime.h>
#include <math.h>

// ---------------------------------------------------------------------------
// MLA attention, fp32 baseline.
// B=4, T=2048, C=1024, H=16, HS=64, DHR=32, head dim = 96.
// ---------------------------------------------------------------------------

#define BT    8192      // B*T
#define CDIM  1024
#define TT    2048
#define NHEAD 16

// Scratch (device globals; no allocation APIs allowed)
__device__ float g_cQ [BT * 4096];
__device__ float g_qC [BT * 1024];
__device__ float g_cKV[BT * 256];
__device__ float g_kC [BT * 1024];
__device__ float g_v  [BT * 1024];
__device__ float g_qR [BT * 512];
__device__ float g_kR [BT * 32];
__device__ float g_y  [BT * 1024];

// ---------------------------------------------------------------------------
// Generic SGEMM: C[M,N] = A[M,K] @ B[K,N], row-major.
// Requires: M % 128 == 0, N % 128 == 0, K % 16 == 0 (true for all call sites).
// ROPE epilogue: C[m,n] *= (cos(ph) + sin(ph)), ph = (m % 2048) * inv(n % 16).
// ---------------------------------------------------------------------------
template <bool ROPE>
__global__ __launch_bounds__(256, 2)
void sgemm_kernel(const float* __restrict__ A, const float* __restrict__ B,
                  float* __restrict__ C, int M, int N, int K)
{
    __shared__ float As[16][128];
    __shared__ float Bs[16][132];   // +4 pad

    const int tid = threadIdx.x;
    const int tx = tid & 15;        // N direction
    const int ty = tid >> 4;        // M direction
    const int bx = blockIdx.x;      // N tile
    const int by = blockIdx.y;      // M tile

    const float* Ap = A + (size_t)by * 128 * K;
    const float* Bp = B + (size_t)bx * 128;

    float acc[8][8];
#pragma unroll
    for (int i = 0; i < 8; i++)
#pragma unroll
        for (int j = 0; j < 8; j++) acc[i][j] = 0.f;

    for (int k0 = 0; k0 < K; k0 += 16) {
        // A tile 128x16 -> As[k][m] (transposed)
#pragma unroll
        for (int u = 0; u < 2; u++) {
            int idx = tid * 2 + u;                 // 0..511
            int r = idx >> 2;                      // 0..127
            int c = (idx & 3) << 2;                // 0,4,8,12
            float4 f = *(const float4*)(Ap + (size_t)r * K + (k0 + c));
            As[c + 0][r] = f.x; As[c + 1][r] = f.y;
            As[c + 2][r] = f.z; As[c + 3][r] = f.w;
        }
        // B tile 16x128 -> Bs[k][n]
#pragma unroll
        for (int u = 0; u < 2; u++) {
            int idx = tid * 2 + u;                 // 0..511
            int r = idx >> 5;                      // 0..15
            int c = (idx & 31) << 2;               // 0..124
            *(float4*)&Bs[r][c] = *(const float4*)(Bp + (size_t)(k0 + r) * N + c);
        }
        __syncthreads();

#pragma unroll
        for (int k = 0; k < 16; k++) {
            float a[8], b[8];
            *(float4*)&a[0] = *(float4*)&As[k][ty * 4];
            *(float4*)&a[4] = *(float4*)&As[k][64 + ty * 4];
            *(float4*)&b[0] = *(float4*)&Bs[k][tx * 4];
            *(float4*)&b[4] = *(float4*)&Bs[k][64 + tx * 4];
#pragma unroll
            for (int i = 0; i < 8; i++)
#pragma unroll
                for (int j = 0; j < 8; j++) acc[i][j] += a[i] * b[j];
        }
        __syncthreads();
    }

    if (!ROPE) {
#pragma unroll
        for (int i = 0; i < 8; i++) {
            int m = by * 128 + ((i < 4) ? (ty * 4 + i) : (64 + ty * 4 + i - 4));
            float* Cr = C + (size_t)m * N + bx * 128;
            *(float4*)&Cr[tx * 4]      = make_float4(acc[i][0], acc[i][1], acc[i][2], acc[i][3]);
            *(float4*)&Cr[64 + tx * 4] = make_float4(acc[i][4], acc[i][5], acc[i][6], acc[i][7]);
        }
    } else {
        float invf[8];
        int   ncol[8];
#pragma unroll
        for (int j = 0; j < 8; j++) {
            int n = bx * 128 + ((j < 4) ? (tx * 4 + j) : (64 + tx * 4 + j - 4));
            ncol[j] = n;
            invf[j] = 1.0f / powf(10000.0f, (float)(n & 15) * 0.0625f);
        }
#pragma unroll
        for (int i = 0; i < 8; i++) {
            int m = by * 128 + ((i < 4) ? (ty * 4 + i) : (64 + ty * 4 + i - 4));
            float tf = (float)(m & (TT - 1));
            float* Cr = C + (size_t)m * N;
#pragma unroll
            for (int j = 0; j < 8; j++) {
                float ph = tf * invf[j];
                float sn, cs;
                sincosf(ph, &sn, &cs);
                Cr[ncol[j]] = acc[i][j] * (cs + sn);
            }
        }
    }
}

// ---------------------------------------------------------------------------
// k_R = (x @ W_KR) * rope_scale   (K=1024, N=32). grid=1024, block=256 (8 rows).
// ---------------------------------------------------------------------------
__global__ void kr_kernel(const float* __restrict__ x, const float* __restrict__ Wkr,
                          float* __restrict__ out)
{
    int m = blockIdx.x * 8 + (threadIdx.x >> 5);
    int n = threadIdx.x & 31;
    const float* xr = x + (size_t)m * CDIM;
    float s = 0.f;
#pragma unroll 8
    for (int k = 0; k < CDIM; k++) s += xr[k] * Wkr[k * 32 + n];
    float inv = 1.0f / powf(10000.0f, (float)(n & 15) * 0.0625f);
    float ph = (float)(m & (TT - 1)) * inv;
    float sn, cs;
    sincosf(ph, &sn, &cs);
    out[(size_t)m * 32 + n] = s * (cs + sn);
}

// ---------------------------------------------------------------------------
// Causal flash attention, head dim 96 (64 compressed + 32 rotary), V dim 64.
// grid = (T/64, H, B), block = 256. Q tile 64 x 96, KV tile 64.
// Thread (tx,ty): owns 4x4 of scores (qr=ty*4.., kc=tx*4..) and of O (qr, d).
// ---------------------------------------------------------------------------
#define QK_LD 68   // padded row stride for d-major Q/K tiles
#define S_LD  68   // padded row stride for S[kc][qr]

__global__ __launch_bounds__(256, 2)
void attn_kernel(const float* __restrict__ qC, const float* __restrict__ qR,
                 const float* __restrict__ kC, const float* __restrict__ kR,
                 const float* __restrict__ V, float* __restrict__ Y)
{
    extern __shared__ float sm[];
    float* Qs = sm;                    // [96][QK_LD]  (d-major: Qs[d][qr])
    float* Ks = Qs + 96 * QK_LD;       // [96][QK_LD]  (d-major: Ks[d][kc])
    float* Vs = Ks + 96 * QK_LD;       // [64][64]     (Vs[kc][d])
    float* S  = Vs + 64 * 64;          // [64][S_LD]   (S[kc][qr])
    float* alphabuf = S + 64 * S_LD;   // [64]
    float* lbuf     = alphabuf + 64;   // [64]

    const int qt = blockIdx.x, h = blockIdx.y, b = blockIdx.z;
    const int tid = threadIdx.x;
    const int tx = tid & 15, ty = tid >> 4;
    const int q0 = qt * 64;
    const size_t rowB = (size_t)b * TT;

    // Load Q tile once: d<64 from qC head slice, d>=64 from qR head slice.
    for (int idx = tid; idx < 96 * 64; idx += 256) {
        int qr = idx / 96, d = idx % 96;
        size_t row = rowB + q0 + qr;
        float val = (d < 64) ? qC[row * 1024 + h * 64 + d]
                             : qR[row * 512 + h * 32 + (d - 64)];
        Qs[d * QK_LD + qr] = val;
    }

    float accO[4][4];
#pragma unroll
    for (int i = 0; i < 4; i++)
#pragma unroll
        for (int j = 0; j < 4; j++) accO[i][j] = 0.f;
    float mrow = -1e30f, lrow = 0.f;         // valid for tid < 64
    const float rscale = rsqrtf(96.0f);
    __syncthreads();

    for (int kt = 0; kt <= qt; kt++) {
        const size_t krow0 = rowB + kt * 64;
        // Load K tile (d-major) and V tile
        for (int idx = tid; idx < 96 * 64; idx += 256) {
            int kc = idx / 96, d = idx % 96;
            size_t row = krow0 + kc;
            float val = (d < 64) ? kC[row * 1024 + h * 64 + d]
                                 : kR[row * 32 + (d - 64)];
            Ks[d * QK_LD + kc] = val;
        }
        for (int idx = tid; idx < 64 * 16; idx += 256) {
            int kc = idx >> 4, d4 = (idx & 15) << 2;
            *(float4*)&Vs[kc * 64 + d4] =
                *(const float4*)&V[(krow0 + kc) * 1024 + h * 64 + d4];
        }
        __syncthreads();

        // Scores: s[i][j] = sum_d Q[qr][d] * K[kc][d]
        float s[4][4];
#pragma unroll
        for (int i = 0; i < 4; i++)
#pragma unroll
            for (int j = 0; j < 4; j++) s[i][j] = 0.f;
#pragma unroll 4
        for (int d = 0; d < 96; d++) {
            float qa[4], ka[4];
            *(float4*)qa = *(float4*)&Qs[d * QK_LD + ty * 4];
            *(float4*)ka = *(float4*)&Ks[d * QK_LD + tx * 4];
#pragma unroll
            for (int i = 0; i < 4; i++)
#pragma unroll
                for (int j = 0; j < 4; j++) s[i][j] += qa[i] * ka[j];
        }
        // Write transposed: S[kc][qr]
#pragma unroll
        for (int j = 0; j < 4; j++)
            *(float4*)&S[(tx * 4 + j) * S_LD + ty * 4] =
                make_float4(s[0][j], s[1][j], s[2][j], s[3][j]);
        __syncthreads();

        // Online softmax: one thread per q row (threads 0..63)
        if (tid < 64) {
            int r = tid;
            int nvalid = q0 + r - kt * 64 + 1;   // causal: k <= q
            if (nvalid > 64) nvalid = 64;
            float rowmax = -1e30f;
            for (int kc = 0; kc < nvalid; kc++)
                rowmax = fmaxf(rowmax, S[kc * S_LD + r]);
            float mNew  = fmaxf(mrow, rowmax * rscale);
            float alpha = expf(mrow - mNew);
            float sum = 0.f;
            for (int kc = 0; kc < 64; kc++) {
                float p = (kc < nvalid) ? expf(S[kc * S_LD + r] * rscale - mNew) : 0.f;
                S[kc * S_LD + r] = p;
                sum += p;
            }
            lrow = lrow * alpha + sum;
            mrow = mNew;
            alphabuf[r] = alpha;
        }
        __syncthreads();

        // Rescale accumulators + P @ V
        float al[4];
#pragma unroll
        for (int i = 0; i < 4; i++) al[i] = alphabuf[ty * 4 + i];
#pragma unroll
        for (int i = 0; i < 4; i++)
#pragma unroll
            for (int j = 0; j < 4; j++) accO[i][j] *= al[i];
#pragma unroll 4
        for (int kc = 0; kc < 64; kc++) {
            float pa[4], va[4];
            *(float4*)pa = *(float4*)&S[kc * S_LD + ty * 4];
            *(float4*)va = *(float4*)&Vs[kc * 64 + tx * 4];
#pragma unroll
            for (int i = 0; i < 4; i++)
#pragma unroll
                for (int j = 0; j < 4; j++) accO[i][j] += pa[i] * va[j];
        }
        __syncthreads();
    }

    if (tid < 64) lbuf[tid] = lrow;
    __syncthreads();

#pragma unroll
    for (int i = 0; i < 4; i++) {
        int qr = ty * 4 + i;
        float invl = 1.0f / lbuf[qr];
        size_t row = rowB + q0 + qr;
        *(float4*)&Y[row * 1024 + h * 64 + tx * 4] =
            make_float4(accO[i][0] * invl, accO[i][1] * invl,
                        accO[i][2] * invl, accO[i][3] * invl);
    }
}

// ---------------------------------------------------------------------------
// Launcher
// ---------------------------------------------------------------------------
extern "C" void kernel_launch(void* const* d_in, const int* in_sizes, int n_in,
                              void* d_out, int out_size)
{
    const float* x     = (const float*)d_in[0];
    const float* W_DQ  = (const float*)d_in[1];
    const float* W_UQ  = (const float*)d_in[2];
    const float* W_DKV = (const float*)d_in[3];
    const float* W_UK  = (const float*)d_in[4];
    const float* W_UV  = (const float*)d_in[5];
    const float* W_QR  = (const float*)d_in[6];
    const float* W_KR  = (const float*)d_in[7];
    const float* W_O   = (const float*)d_in[8];
    float* out = (float*)d_out;

    float *cQ, *qC, *cKV, *kC, *v, *qR, *kR, *y;
    cudaGetSymbolAddress((void**)&cQ,  g_cQ);
    cudaGetSymbolAddress((void**)&qC,  g_qC);
    cudaGetSymbolAddress((void**)&cKV, g_cKV);
    cudaGetSymbolAddress((void**)&kC,  g_kC);
    cudaGetSymbolAddress((void**)&v,   g_v);
    cudaGetSymbolAddress((void**)&qR,  g_qR);
    cudaGetSymbolAddress((void**)&kR,  g_kR);
    cudaGetSymbolAddress((void**)&y,   g_y);

    const int SMEM_ATTN = (96 * QK_LD * 2 + 64 * 64 + 64 * S_LD + 128) * 4;
    cudaFuncSetAttribute(attn_kernel,
                         cudaFuncAttributeMaxDynamicSharedMemorySize, SMEM_ATTN);

    dim3 blk(256);

    // 1. c_Q = x @ W_DQ            (8192 x 4096 x 1024)
    sgemm_kernel<false><<<dim3(4096 / 128, BT / 128), blk>>>(x, W_DQ, cQ, BT, 4096, 1024);
    // 2. q_C = c_Q @ W_UQ          (8192 x 1024 x 4096)
    sgemm_kernel<false><<<dim3(1024 / 128, BT / 128), blk>>>(cQ, W_UQ, qC, BT, 1024, 4096);
    // 3. c_KV = x @ W_DKV          (8192 x 256 x 1024)
    sgemm_kernel<false><<<dim3(256 / 128, BT / 128), blk>>>(x, W_DKV, cKV, BT, 256, 1024);
    // 4. k_C = c_KV @ W_UK         (8192 x 1024 x 256)
    sgemm_kernel<false><<<dim3(1024 / 128, BT / 128), blk>>>(cKV, W_UK, kC, BT, 1024, 256);
    // 5. v = c_KV @ W_UV           (8192 x 1024 x 256)
    sgemm_kernel<false><<<dim3(1024 / 128, BT / 128), blk>>>(cKV, W_UV, v, BT, 1024, 256);
    // 6. q_R = (c_Q @ W_QR) * rope (8192 x 512 x 4096)
    sgemm_kernel<true><<<dim3(512 / 128, BT / 128), blk>>>(cQ, W_QR, qR, BT, 512, 4096);
    // 7. k_R = (x @ W_KR) * rope   (8192 x 32 x 1024)
    kr_kernel<<<BT / 8, 256>>>(x, W_KR, kR);
    // 8. attention -> y
    attn_kernel<<<dim3(TT / 64, NHEAD, 4), blk, SMEM_ATTN>>>(qC, qR, kC, kR, v, y);
    // 9. out = y @ W_O             (8192 x 1024 x 1024)
    sgemm_kernel<false><<<dim3(1024 / 128, BT / 128), blk>>>(y, W_O, out, BT, 1024, 1024);
}

// round 3
// speedup vs baseline: 2.0539x; 2.0539x over previous
#include <cuda_runtime.h>
#include <math.h>
#include <stdint.h>

// ---------------------------------------------------------------------------
// MLA attention, tf32 tensor-core version.
// B=4, T=2048, C=1024, H=16, HS=64, DHR=32, head dim = 96.
// ---------------------------------------------------------------------------

#define BT    8192
#define TT    2048
#define NHEAD 16

// Scratch
__device__ float g_cQ [(size_t)BT * 4096];
__device__ float g_qC [(size_t)BT * 1024];
__device__ float g_cKV[(size_t)BT * 256];
__device__ float g_kC [(size_t)BT * 1024];
__device__ float g_v  [(size_t)BT * 1024];
__device__ float g_qR [(size_t)BT * 512];
__device__ float g_kR [(size_t)BT * 32];
__device__ float g_y  [(size_t)BT * 1024];
__device__ float g_rope[TT * 16];

// ---------------------------------------------------------------------------
// Helpers
// ---------------------------------------------------------------------------
__device__ __forceinline__ uint32_t f2tf(float x) {
    uint32_t r;
    asm("cvt.rna.tf32.f32 %0, %1;" : "=r"(r) : "f"(x));
    return r;
}

__device__ __forceinline__ void mma8(float* c, uint32_t a0, uint32_t a1,
                                     uint32_t a2, uint32_t a3,
                                     uint32_t b0, uint32_t b1) {
    asm volatile(
        "mma.sync.aligned.m16n8k8.row.col.f32.tf32.tf32.f32 "
        "{%0,%1,%2,%3}, {%4,%5,%6,%7}, {%8,%9}, {%0,%1,%2,%3};"
        : "+f"(c[0]), "+f"(c[1]), "+f"(c[2]), "+f"(c[3])
        : "r"(a0), "r"(a1), "r"(a2), "r"(a3), "r"(b0), "r"(b1));
}

// exp on the FMA pipe (exp2 split + deg-5 poly), rel err ~2e-6.
__device__ __forceinline__ float fast_exp(float x) {
    float y = fmaxf(x * 1.4426950408889634f, -126.0f);
    float z = y + 12582912.0f;                 // round-to-nearest via magic
    int   n = __float_as_int(z) - 0x4B400000;  // integer part
    float f = y - (z - 12582912.0f);           // frac in [-0.5, 0.5]
    float p = 1.33336498e-3f;
    p = fmaf(p, f, 9.61817697e-3f);
    p = fmaf(p, f, 5.55041087e-2f);
    p = fmaf(p, f, 2.40226510e-1f);
    p = fmaf(p, f, 6.93147181e-1f);
    p = fmaf(p, f, 1.0f);
    return __int_as_float(__float_as_int(p) + (n << 23));
}

// ---------------------------------------------------------------------------
// RoPE scale table: rope[t][j] = cos(t * inv_j) + sin(t * inv_j)
// ---------------------------------------------------------------------------
__global__ void rope_kernel(float* rope) {
    int idx = blockIdx.x * 256 + threadIdx.x;
    if (idx >= TT * 16) return;
    int t = idx >> 4, j = idx & 15;
    double inv = pow(10000.0, -(double)j / 16.0);
    float ph = (float)t * (float)inv;
    rope[idx] = cosf(ph) + sinf(ph);
}

// ---------------------------------------------------------------------------
// tf32 GEMM: C[M,N] = A[M,K] @ B[K,N], row-major. M%128==0, N%128==0, K%16==0.
// CTA 128x128, 8 warps as 4(M) x 2(N), warp tile 32x64, mma m16n8k8.
// ---------------------------------------------------------------------------
#define AS_LD 20    // conflict-free stride for A fragment pattern
#define BS_LD 136   // conflict-free stride for B fragment pattern

template <bool ROPE>
__global__ __launch_bounds__(256, 2)
void gemm_tf32(const float* __restrict__ A, const float* __restrict__ B,
               float* __restrict__ C, const float* __restrict__ rope,
               int M, int N, int K)
{
    __shared__ uint32_t As[128 * AS_LD];
    __shared__ uint32_t Bs[16 * BS_LD];

    const int tid = threadIdx.x;
    const int warp = tid >> 5, lane = tid & 31;
    const int wm = warp >> 1, wn = warp & 1;
    const int lr = lane >> 2, lc = lane & 3;
    const int bx = blockIdx.x, by = blockIdx.y;

    float acc[2][8][4];
#pragma unroll
    for (int i = 0; i < 2; i++)
#pragma unroll
        for (int j = 0; j < 8; j++)
#pragma unroll
            for (int q = 0; q < 4; q++) acc[i][j][q] = 0.f;

    const float* Ap = A + (size_t)(by * 128) * K;
    const float* Bp = B + bx * 128;

    for (int k0 = 0; k0 < K; k0 += 16) {
        // A: 128x16 -> As[r][k], tf32
#pragma unroll
        for (int u = 0; u < 2; u++) {
            int idx = tid * 2 + u;              // 0..511
            int r = idx >> 2, c = (idx & 3) << 2;
            float4 f = *(const float4*)(Ap + (size_t)r * K + k0 + c);
            uint32_t* dst = &As[r * AS_LD + c];
            dst[0] = f2tf(f.x); dst[1] = f2tf(f.y);
            dst[2] = f2tf(f.z); dst[3] = f2tf(f.w);
        }
        // B: 16x128 -> Bs[k][n], tf32
#pragma unroll
        for (int u = 0; u < 2; u++) {
            int idx = tid * 2 + u;
            int r = idx >> 5, c = (idx & 31) << 2;
            float4 f = *(const float4*)(Bp + (size_t)(k0 + r) * N + c);
            uint32_t* dst = &Bs[r * BS_LD + c];
            dst[0] = f2tf(f.x); dst[1] = f2tf(f.y);
            dst[2] = f2tf(f.z); dst[3] = f2tf(f.w);
        }
        __syncthreads();

#pragma unroll
        for (int ks = 0; ks < 2; ks++) {
            int kk = ks * 8;
            uint32_t af[2][4];
#pragma unroll
            for (int i = 0; i < 2; i++) {
                int r = wm * 32 + i * 16 + lr;
                af[i][0] = As[r * AS_LD + kk + lc];
                af[i][1] = As[(r + 8) * AS_LD + kk + lc];
                af[i][2] = As[r * AS_LD + kk + lc + 4];
                af[i][3] = As[(r + 8) * AS_LD + kk + lc + 4];
            }
#pragma unroll
            for (int j = 0; j < 8; j++) {
                int n = wn * 64 + j * 8 + lr;
                uint32_t b0 = Bs[(kk + lc) * BS_LD + n];
                uint32_t b1 = Bs[(kk + lc + 4) * BS_LD + n];
#pragma unroll
                for (int i = 0; i < 2; i++)
                    mma8(acc[i][j], af[i][0], af[i][1], af[i][2], af[i][3], b0, b1);
            }
        }
        __syncthreads();
    }

#pragma unroll
    for (int i = 0; i < 2; i++) {
        int r0 = by * 128 + wm * 32 + i * 16 + lr;
#pragma unroll
        for (int j = 0; j < 8; j++) {
            int c0 = bx * 128 + wn * 64 + j * 8 + lc * 2;
            if (!ROPE) {
                *(float2*)(C + (size_t)r0 * N + c0)       = make_float2(acc[i][j][0], acc[i][j][1]);
                *(float2*)(C + (size_t)(r0 + 8) * N + c0) = make_float2(acc[i][j][2], acc[i][j][3]);
            } else {
                float s0 = rope[(r0 & (TT - 1)) * 16 + (c0 & 15)];
                float s1 = rope[(r0 & (TT - 1)) * 16 + ((c0 + 1) & 15)];
                float s2 = rope[((r0 + 8) & (TT - 1)) * 16 + (c0 & 15)];
                float s3 = rope[((r0 + 8) & (TT - 1)) * 16 + ((c0 + 1) & 15)];
                *(float2*)(C + (size_t)r0 * N + c0)       = make_float2(acc[i][j][0] * s0, acc[i][j][1] * s1);
                *(float2*)(C + (size_t)(r0 + 8) * N + c0) = make_float2(acc[i][j][2] * s2, acc[i][j][3] * s3);
            }
        }
    }
}

// ---------------------------------------------------------------------------
// k_R = (x @ W_KR) * rope   (8192 x 32, K=1024)
// ---------------------------------------------------------------------------
__global__ void kr_kernel(const float* __restrict__ x, const float* __restrict__ Wkr,
                          const float* __restrict__ rope, float* __restrict__ out)
{
    int m = blockIdx.x * 8 + (threadIdx.x >> 5);
    int n = threadIdx.x & 31;
    const float* xr = x + (size_t)m * 1024;
    float s = 0.f;
#pragma unroll 8
    for (int k = 0; k < 1024; k++) s += xr[k] * Wkr[k * 32 + n];
    out[(size_t)m * 32 + n] = s * rope[(m & (TT - 1)) * 16 + (n & 15)];
}

// ---------------------------------------------------------------------------
// Causal flash attention with tf32 mma. Q tile 64 x 96, KV tile 64, V dim 64.
// grid = (T/64, H, B), 256 threads = 8 warps: wm = warp&3 (16-row strip),
// wn = warp>>2 (32-col half).
// ---------------------------------------------------------------------------
#define Q_LD 100
#define K_LD 100
#define V_LD 72
#define S_LD 68
#define SMEM_ATTN_WORDS (64*Q_LD + 64*K_LD + 64*V_LD + 64*S_LD + 192)

__global__ __launch_bounds__(256, 2)
void attn_mma(const float* __restrict__ qC, const float* __restrict__ qR,
              const float* __restrict__ kC, const float* __restrict__ kR,
              const float* __restrict__ V, float* __restrict__ Y)
{
    extern __shared__ uint32_t sm[];
    uint32_t* Qs = sm;
    uint32_t* Ks = Qs + 64 * Q_LD;
    uint32_t* Vs = Ks + 64 * K_LD;
    uint32_t* Ss = Vs + 64 * V_LD;     // scores (float bits), then P (tf32 bits)
    float* mbuf = (float*)(Ss + 64 * S_LD);
    float* lbuf = mbuf + 64;
    float* abuf = lbuf + 64;

    const int qt = blockIdx.x, h = blockIdx.y, b = blockIdx.z;
    const int tid = threadIdx.x, warp = tid >> 5, lane = tid & 31;
    const int lr = lane >> 2, lc = lane & 3;
    const int wm = warp & 3, wn = warp >> 2;
    const int q0 = qt * 64;
    const size_t rowB = (size_t)b * TT;

    // Q tile (64 x 96): d<64 from qC, d>=64 from qR
    for (int idx = tid; idx < 64 * 96; idx += 256) {
        int qr = idx / 96, d = idx - qr * 96;
        size_t row = rowB + q0 + qr;
        float v = (d < 64) ? qC[row * 1024 + h * 64 + d]
                           : qR[row * 512 + h * 32 + d - 64];
        Qs[qr * Q_LD + d] = f2tf(v);
    }
    if (tid < 64) { mbuf[tid] = -1e30f; lbuf[tid] = 0.f; }

    float accO[4][4];
#pragma unroll
    for (int j = 0; j < 4; j++)
#pragma unroll
        for (int q = 0; q < 4; q++) accO[j][q] = 0.f;

    const float rscale = 0.10206207261596575f;  // 1/sqrt(96)
    __syncthreads();

    for (int kt = 0; kt <= qt; kt++) {
        const size_t kr0 = rowB + kt * 64;
        // K tile (64 x 96)
        for (int idx = tid; idx < 64 * 96; idx += 256) {
            int kc = idx / 96, d = idx - kc * 96;
            size_t row = kr0 + kc;
            float v = (d < 64) ? kC[row * 1024 + h * 64 + d]
                               : kR[row * 32 + d - 64];
            Ks[kc * K_LD + d] = f2tf(v);
        }
        // V tile (64 x 64)
        for (int idx = tid; idx < 64 * 64; idx += 256) {
            int kc = idx >> 6, d = idx & 63;
            Vs[kc * V_LD + d] = f2tf(V[(kr0 + kc) * 1024 + h * 64 + d]);
        }
        __syncthreads();

        // S = Q @ K^T  (64x64, k=96)
        float sacc[4][4];
#pragma unroll
        for (int j = 0; j < 4; j++)
#pragma unroll
            for (int q = 0; q < 4; q++) sacc[j][q] = 0.f;

        {
            int r = wm * 16 + lr;
#pragma unroll
            for (int ks = 0; ks < 12; ks++) {
                int d0 = ks * 8;
                uint32_t a0 = Qs[r * Q_LD + d0 + lc];
                uint32_t a1 = Qs[(r + 8) * Q_LD + d0 + lc];
                uint32_t a2 = Qs[r * Q_LD + d0 + lc + 4];
                uint32_t a3 = Qs[(r + 8) * Q_LD + d0 + lc + 4];
#pragma unroll
                for (int j = 0; j < 4; j++) {
                    int n = wn * 32 + j * 8 + lr;
                    uint32_t b0 = Ks[n * K_LD + d0 + lc];
                    uint32_t b1 = Ks[n * K_LD + d0 + lc + 4];
                    mma8(sacc[j], a0, a1, a2, a3, b0, b1);
                }
            }
            // store scaled scores
#pragma unroll
            for (int j = 0; j < 4; j++) {
                int c = wn * 32 + j * 8 + lc * 2;
                *(float2*)(Ss + r * S_LD + c) =
                    make_float2(sacc[j][0] * rscale, sacc[j][1] * rscale);
                *(float2*)(Ss + (r + 8) * S_LD + c) =
                    make_float2(sacc[j][2] * rscale, sacc[j][3] * rscale);
            }
        }
        __syncthreads();

        // Online softmax: 4 threads per row
        {
            int r = tid >> 2, seg = tid & 3;
            float* Sf = (float*)Ss;
            int nvalid = q0 + r - kt * 64 + 1;
            if (nvalid > 64) nvalid = 64;
            float m_old = mbuf[r], l_old = lbuf[r];
            int c0 = seg * 16;
            float pm = -1e30f;
#pragma unroll
            for (int c = 0; c < 16; c++) {
                int cc = c0 + c;
                float s = Sf[r * S_LD + cc];
                pm = (cc < nvalid) ? fmaxf(pm, s) : pm;
            }
            pm = fmaxf(pm, __shfl_xor_sync(0xffffffffu, pm, 1));
            pm = fmaxf(pm, __shfl_xor_sync(0xffffffffu, pm, 2));
            float m_new = fmaxf(m_old, pm);
            float alpha = fast_exp(m_old - m_new);
            float psum = 0.f;
#pragma unroll
            for (int c = 0; c < 16; c++) {
                int cc = c0 + c;
                float p = (cc < nvalid) ? fast_exp(Sf[r * S_LD + cc] - m_new) : 0.f;
                psum += p;
                Ss[r * S_LD + cc] = f2tf(p);
            }
            psum += __shfl_xor_sync(0xffffffffu, psum, 1);
            psum += __shfl_xor_sync(0xffffffffu, psum, 2);
            mbuf[r] = m_new;                 // all 4 threads write same value
            lbuf[r] = l_old * alpha + psum;
            abuf[r] = alpha;
        }
        __syncthreads();

        // Rescale O and accumulate P @ V
        {
            int r = wm * 16 + lr;
            float al0 = abuf[r], al1 = abuf[r + 8];
#pragma unroll
            for (int j = 0; j < 4; j++) {
                accO[j][0] *= al0; accO[j][1] *= al0;
                accO[j][2] *= al1; accO[j][3] *= al1;
            }
#pragma unroll
            for (int ks = 0; ks < 8; ks++) {
                int c0 = ks * 8;
                uint32_t a0 = Ss[r * S_LD + c0 + lc];
                uint32_t a1 = Ss[(r + 8) * S_LD + c0 + lc];
                uint32_t a2 = Ss[r * S_LD + c0 + lc + 4];
                uint32_t a3 = Ss[(r + 8) * S_LD + c0 + lc + 4];
#pragma unroll
                for (int j = 0; j < 4; j++) {
                    int n = wn * 32 + j * 8 + lr;
                    uint32_t b0 = Vs[(c0 + lc) * V_LD + n];
                    uint32_t b1 = Vs[(c0 + lc + 4) * V_LD + n];
                    mma8(accO[j], a0, a1, a2, a3, b0, b1);
                }
            }
        }
        __syncthreads();
    }

    // Epilogue: divide by l, write Y
    {
        int r = wm * 16 + lr;
        float il0 = 1.f / lbuf[r], il1 = 1.f / lbuf[r + 8];
#pragma unroll
        for (int j = 0; j < 4; j++) {
            int c = h * 64 + wn * 32 + j * 8 + lc * 2;
            size_t row0 = rowB + q0 + r;
            *(float2*)(Y + row0 * 1024 + c) =
                make_float2(accO[j][0] * il0, accO[j][1] * il0);
            *(float2*)(Y + (row0 + 8) * 1024 + c) =
                make_float2(accO[j][2] * il1, accO[j][3] * il1);
        }
    }
}

// ---------------------------------------------------------------------------
// Launcher
// ---------------------------------------------------------------------------
extern "C" void kernel_launch(void* const* d_in, const int* in_sizes, int n_in,
                              void* d_out, int out_size)
{
    const float* x     = (const float*)d_in[0];
    const float* W_DQ  = (const float*)d_in[1];
    const float* W_UQ  = (const float*)d_in[2];
    const float* W_DKV = (const float*)d_in[3];
    const float* W_UK  = (const float*)d_in[4];
    const float* W_UV  = (const float*)d_in[5];
    const float* W_QR  = (const float*)d_in[6];
    const float* W_KR  = (const float*)d_in[7];
    const float* W_O   = (const float*)d_in[8];
    float* out = (float*)d_out;

    float *cQ, *qC, *cKV, *kC, *v, *qR, *kR, *y, *rope;
    cudaGetSymbolAddress((void**)&cQ,  g_cQ);
    cudaGetSymbolAddress((void**)&qC,  g_qC);
    cudaGetSymbolAddress((void**)&cKV, g_cKV);
    cudaGetSymbolAddress((void**)&kC,  g_kC);
    cudaGetSymbolAddress((void**)&v,   g_v);
    cudaGetSymbolAddress((void**)&qR,  g_qR);
    cudaGetSymbolAddress((void**)&kR,  g_kR);
    cudaGetSymbolAddress((void**)&y,   g_y);
    cudaGetSymbolAddress((void**)&rope, g_rope);

    const int SMEM_ATTN = SMEM_ATTN_WORDS * 4;
    cudaFuncSetAttribute(attn_mma,
                         cudaFuncAttributeMaxDynamicSharedMemorySize, SMEM_ATTN);

    dim3 blk(256);

    rope_kernel<<<(TT * 16 + 255) / 256, 256>>>(rope);

    // 1. c_Q = x @ W_DQ            (8192 x 4096 x 1024)
    gemm_tf32<false><<<dim3(32, 64), blk>>>(x, W_DQ, cQ, rope, BT, 4096, 1024);
    // 2. q_C = c_Q @ W_UQ          (8192 x 1024 x 4096)
    gemm_tf32<false><<<dim3(8, 64), blk>>>(cQ, W_UQ, qC, rope, BT, 1024, 4096);
    // 3. c_KV = x @ W_DKV          (8192 x 256 x 1024)
    gemm_tf32<false><<<dim3(2, 64), blk>>>(x, W_DKV, cKV, rope, BT, 256, 1024);
    // 4. k_C = c_KV @ W_UK         (8192 x 1024 x 256)
    gemm_tf32<false><<<dim3(8, 64), blk>>>(cKV, W_UK, kC, rope, BT, 1024, 256);
    // 5. v = c_KV @ W_UV           (8192 x 1024 x 256)
    gemm_tf32<false><<<dim3(8, 64), blk>>>(cKV, W_UV, v, rope, BT, 1024, 256);
    // 6. q_R = (c_Q @ W_QR) * rope (8192 x 512 x 4096)
    gemm_tf32<true><<<dim3(4, 64), blk>>>(cQ, W_QR, qR, rope, BT, 512, 4096);
    // 7. k_R = (x @ W_KR) * rope   (8192 x 32 x 1024)
    kr_kernel<<<BT / 8, 256>>>(x, W_KR, rope, kR);
    // 8. attention -> y
    attn_mma<<<dim3(TT / 64, NHEAD, 4), blk, SMEM_ATTN>>>(qC, qR, kC, kR, v, y);
    // 9. out = y @ W_O             (8192 x 1024 x 1024)
    gemm_tf32<false><<<dim3(8, 64), blk>>>(y, W_O, out, rope, BT, 1024, 1024);
}

// round 5
// speedup vs baseline: 2.2005x; 1.0714x over previous
#include <cuda_runtime.h>
#include <math.h>
#include <stdint.h>

// ---------------------------------------------------------------------------
// MLA attention, tf32 tensor-core version with cp.async pipelined GEMM.
// B=4, T=2048, C=1024, H=16, HS=64, DHR=32, head dim = 96.
// ---------------------------------------------------------------------------

#define BT    8192
#define TT    2048
#define NHEAD 16

// Scratch
__device__ float g_cQ [(size_t)BT * 4096];
__device__ float g_qC [(size_t)BT * 1024];
__device__ float g_cKV[(size_t)BT * 256];
__device__ float g_kC [(size_t)BT * 1024];
__device__ float g_v  [(size_t)BT * 1024];
__device__ float g_qR [(size_t)BT * 512];
__device__ float g_kR [(size_t)BT * 32];
__device__ float g_y  [(size_t)BT * 1024];
__device__ float g_rope[TT * 16];

// ---------------------------------------------------------------------------
// Helpers
// ---------------------------------------------------------------------------
__device__ __forceinline__ uint32_t f2tf(float x) {
    uint32_t r;
    asm("cvt.rna.tf32.f32 %0, %1;" : "=r"(r) : "f"(x));
    return r;
}

__device__ __forceinline__ void mma8(float* c, uint32_t a0, uint32_t a1,
                                     uint32_t a2, uint32_t a3,
                                     uint32_t b0, uint32_t b1) {
    asm volatile(
        "mma.sync.aligned.m16n8k8.row.col.f32.tf32.tf32.f32 "
        "{%0,%1,%2,%3}, {%4,%5,%6,%7}, {%8,%9}, {%0,%1,%2,%3};"
        : "+f"(c[0]), "+f"(c[1]), "+f"(c[2]), "+f"(c[3])
        : "r"(a0), "r"(a1), "r"(a2), "r"(a3), "r"(b0), "r"(b1));
}

__device__ __forceinline__ void cp16(float* dst, const float* src) {
    uint32_t d = (uint32_t)__cvta_generic_to_shared(dst);
    asm volatile("cp.async.ca.shared.global [%0], [%1], 16;" :: "r"(d), "l"(src));
}
#define CP_COMMIT() asm volatile("cp.async.commit_group;")
#define CP_WAIT1()  asm volatile("cp.async.wait_group 1;")

// exp on the FMA pipe (exp2 split + deg-5 poly), rel err ~2e-6.
__device__ __forceinline__ float fast_exp(float x) {
    float y = fmaxf(x * 1.4426950408889634f, -126.0f);
    float z = y + 12582912.0f;
    int   n = __float_as_int(z) - 0x4B400000;
    float f = y - (z - 12582912.0f);
    float p = 1.33336498e-3f;
    p = fmaf(p, f, 9.61817697e-3f);
    p = fmaf(p, f, 5.55041087e-2f);
    p = fmaf(p, f, 2.40226510e-1f);
    p = fmaf(p, f, 6.93147181e-1f);
    p = fmaf(p, f, 1.0f);
    return __int_as_float(__float_as_int(p) + (n << 23));
}

// ---------------------------------------------------------------------------
// RoPE scale table
// ---------------------------------------------------------------------------
__global__ void rope_kernel(float* rope) {
    int idx = blockIdx.x * 256 + threadIdx.x;
    if (idx >= TT * 16) return;
    int t = idx >> 4, j = idx & 15;
    double inv = pow(10000.0, -(double)j / 16.0);
    float ph = (float)t * (float)inv;
    rope[idx] = cosf(ph) + sinf(ph);
}

// ---------------------------------------------------------------------------
// tf32 GEMM, 3-stage cp.async pipeline. C[M,N] = A[M,K] @ B[K,N], row-major.
// M%128==0, N%128==0, K%16==0. CTA 128x128, 8 warps 4(M)x2(N), mma m16n8k8.
// Raw f32 in smem; cvt.rna to tf32 on fragments (numerics identical to R3).
// ---------------------------------------------------------------------------
#define AS_LD  20
#define BS_LD  136
#define STAGES 3
#define A_WORDS (128 * AS_LD)
#define B_WORDS (16 * BS_LD)
#define GEMM_SMEM (STAGES * (A_WORDS + B_WORDS) * 4)

__device__ __forceinline__ void gemm_load_tile(
    float* As, float* Bs, const float* Ap, const float* Bp,
    int k0, int K, int N, int tid)
{
#pragma unroll
    for (int u = 0; u < 2; u++) {
        int idx = tid * 2 + u;              // 0..511
        int r = idx >> 2, c = (idx & 3) << 2;
        cp16(&As[r * AS_LD + c], Ap + (size_t)r * K + k0 + c);
    }
#pragma unroll
    for (int u = 0; u < 2; u++) {
        int idx = tid * 2 + u;
        int r = idx >> 5, c = (idx & 31) << 2;
        cp16(&Bs[r * BS_LD + c], Bp + (size_t)(k0 + r) * N + c);
    }
}

template <bool ROPE>
__global__ __launch_bounds__(256, 2)
void gemm_tf32(const float* __restrict__ A, const float* __restrict__ B,
               float* __restrict__ C, const float* __restrict__ rope,
               int M, int N, int K)
{
    extern __shared__ float smf[];
    float* As = smf;                         // [STAGES][A_WORDS]
    float* Bs = smf + STAGES * A_WORDS;      // [STAGES][B_WORDS]

    const int tid = threadIdx.x;
    const int warp = tid >> 5, lane = tid & 31;
    const int wm = warp >> 1, wn = warp & 1;
    const int lr = lane >> 2, lc = lane & 3;
    const int bx = blockIdx.x, by = blockIdx.y;

    float acc[2][8][4];
#pragma unroll
    for (int i = 0; i < 2; i++)
#pragma unroll
        for (int j = 0; j < 8; j++)
#pragma unroll
            for (int q = 0; q < 4; q++) acc[i][j][q] = 0.f;

    const float* Ap = A + (size_t)(by * 128) * K;
    const float* Bp = B + bx * 128;

    const int ktiles = K >> 4;

    // Prologue: fill first STAGES-1 buffers
#pragma unroll
    for (int s = 0; s < STAGES - 1; s++) {
        gemm_load_tile(As + s * A_WORDS, Bs + s * B_WORDS, Ap, Bp, s * 16, K, N, tid);
        CP_COMMIT();
    }

    for (int kt = 0; kt < ktiles; kt++) {
        CP_WAIT1();
        __syncthreads();

        // Issue next tile's loads first so LDGSTS overlaps the MMAs below.
        int nk = kt + STAGES - 1;
        if (nk < ktiles) {
            int ws = nk % STAGES;
            gemm_load_tile(As + ws * A_WORDS, Bs + ws * B_WORDS, Ap, Bp, nk * 16, K, N, tid);
        }
        CP_COMMIT();

        const float* As_ = As + (kt % STAGES) * A_WORDS;
        const float* Bs_ = Bs + (kt % STAGES) * B_WORDS;

#pragma unroll
        for (int ks = 0; ks < 2; ks++) {
            int kk = ks * 8;
            uint32_t af[2][4];
#pragma unroll
            for (int i = 0; i < 2; i++) {
                int r = wm * 32 + i * 16 + lr;
                af[i][0] = f2tf(As_[r * AS_LD + kk + lc]);
                af[i][1] = f2tf(As_[(r + 8) * AS_LD + kk + lc]);
                af[i][2] = f2tf(As_[r * AS_LD + kk + lc + 4]);
                af[i][3] = f2tf(As_[(r + 8) * AS_LD + kk + lc + 4]);
            }
#pragma unroll
            for (int j = 0; j < 8; j++) {
                int n = wn * 64 + j * 8 + lr;
                uint32_t b0 = f2tf(Bs_[(kk + lc) * BS_LD + n]);
                uint32_t b1 = f2tf(Bs_[(kk + lc + 4) * BS_LD + n]);
#pragma unroll
                for (int i = 0; i < 2; i++)
                    mma8(acc[i][j], af[i][0], af[i][1], af[i][2], af[i][3], b0, b1);
            }
        }
        __syncthreads();
    }

#pragma unroll
    for (int i = 0; i < 2; i++) {
        int r0 = by * 128 + wm * 32 + i * 16 + lr;
#pragma unroll
        for (int j = 0; j < 8; j++) {
            int c0 = bx * 128 + wn * 64 + j * 8 + lc * 2;
            if (!ROPE) {
                *(float2*)(C + (size_t)r0 * N + c0)       = make_float2(acc[i][j][0], acc[i][j][1]);
                *(float2*)(C + (size_t)(r0 + 8) * N + c0) = make_float2(acc[i][j][2], acc[i][j][3]);
            } else {
                float s0 = rope[(r0 & (TT - 1)) * 16 + (c0 & 15)];
                float s1 = rope[(r0 & (TT - 1)) * 16 + ((c0 + 1) & 15)];
                float s2 = rope[((r0 + 8) & (TT - 1)) * 16 + (c0 & 15)];
                float s3 = rope[((r0 + 8) & (TT - 1)) * 16 + ((c0 + 1) & 15)];
                *(float2*)(C + (size_t)r0 * N + c0)       = make_float2(acc[i][j][0] * s0, acc[i][j][1] * s1);
                *(float2*)(C + (size_t)(r0 + 8) * N + c0) = make_float2(acc[i][j][2] * s2, acc[i][j][3] * s3);
            }
        }
    }
}

// ---------------------------------------------------------------------------
// k_R = (x @ W_KR) * rope   (8192 x 32, K=1024)
// ---------------------------------------------------------------------------
__global__ void kr_kernel(const float* __restrict__ x, const float* __restrict__ Wkr,
                          const float* __restrict__ rope, float* __restrict__ out)
{
    int m = blockIdx.x * 8 + (threadIdx.x >> 5);
    int n = threadIdx.x & 31;
    const float* xr = x + (size_t)m * 1024;
    float s = 0.f;
#pragma unroll 8
    for (int k = 0; k < 1024; k++) s += xr[k] * Wkr[k * 32 + n];
    out[(size_t)m * 32 + n] = s * rope[(m & (TT - 1)) * 16 + (n & 15)];
}

// ---------------------------------------------------------------------------
// Causal flash attention with tf32 mma (unchanged from R3).
// ---------------------------------------------------------------------------
#define Q_LD 100
#define K_LD 100
#define V_LD 72
#define S_LD 68
#define SMEM_ATTN_WORDS (64*Q_LD + 64*K_LD + 64*V_LD + 64*S_LD + 192)

__global__ __launch_bounds__(256, 2)
void attn_mma(const float* __restrict__ qC, const float* __restrict__ qR,
              const float* __restrict__ kC, const float* __restrict__ kR,
              const float* __restrict__ V, float* __restrict__ Y)
{
    extern __shared__ uint32_t sm[];
    uint32_t* Qs = sm;
    uint32_t* Ks = Qs + 64 * Q_LD;
    uint32_t* Vs = Ks + 64 * K_LD;
    uint32_t* Ss = Vs + 64 * V_LD;
    float* mbuf = (float*)(Ss + 64 * S_LD);
    float* lbuf = mbuf + 64;
    float* abuf = lbuf + 64;

    const int qt = blockIdx.x, h = blockIdx.y, b = blockIdx.z;
    const int tid = threadIdx.x, warp = tid >> 5, lane = tid & 31;
    const int lr = lane >> 2, lc = lane & 3;
    const int wm = warp & 3, wn = warp >> 2;
    const int q0 = qt * 64;
    const size_t rowB = (size_t)b * TT;

    for (int idx = tid; idx < 64 * 96; idx += 256) {
        int qr = idx / 96, d = idx - qr * 96;
        size_t row = rowB + q0 + qr;
        float v = (d < 64) ? qC[row * 1024 + h * 64 + d]
                           : qR[row * 512 + h * 32 + d - 64];
        Qs[qr * Q_LD + d] = f2tf(v);
    }
    if (tid < 64) { mbuf[tid] = -1e30f; lbuf[tid] = 0.f; }

    float accO[4][4];
#pragma unroll
    for (int j = 0; j < 4; j++)
#pragma unroll
        for (int q = 0; q < 4; q++) accO[j][q] = 0.f;

    const float rscale = 0.10206207261596575f;
    __syncthreads();

    for (int kt = 0; kt <= qt; kt++) {
        const size_t kr0 = rowB + kt * 64;
        for (int idx = tid; idx < 64 * 96; idx += 256) {
            int kc = idx / 96, d = idx - kc * 96;
            size_t row = kr0 + kc;
            float v = (d < 64) ? kC[row * 1024 + h * 64 + d]
                               : kR[row * 32 + d - 64];
            Ks[kc * K_LD + d] = f2tf(v);
        }
        for (int idx = tid; idx < 64 * 64; idx += 256) {
            int kc = idx >> 6, d = idx & 63;
            Vs[kc * V_LD + d] = f2tf(V[(kr0 + kc) * 1024 + h * 64 + d]);
        }
        __syncthreads();

        float sacc[4][4];
#pragma unroll
        for (int j = 0; j < 4; j++)
#pragma unroll
            for (int q = 0; q < 4; q++) sacc[j][q] = 0.f;

        {
            int r = wm * 16 + lr;
#pragma unroll
            for (int ks = 0; ks < 12; ks++) {
                int d0 = ks * 8;
                uint32_t a0 = Qs[r * Q_LD + d0 + lc];
                uint32_t a1 = Qs[(r + 8) * Q_LD + d0 + lc];
                uint32_t a2 = Qs[r * Q_LD + d0 + lc + 4];
                uint32_t a3 = Qs[(r + 8) * Q_LD + d0 + lc + 4];
#pragma unroll
                for (int j = 0; j < 4; j++) {
                    int n = wn * 32 + j * 8 + lr;
                    uint32_t b0 = Ks[n * K_LD + d0 + lc];
                    uint32_t b1 = Ks[n * K_LD + d0 + lc + 4];
                    mma8(sacc[j], a0, a1, a2, a3, b0, b1);
                }
            }
#pragma unroll
            for (int j = 0; j < 4; j++) {
                int c = wn * 32 + j * 8 + lc * 2;
                *(float2*)(Ss + r * S_LD + c) =
                    make_float2(sacc[j][0] * rscale, sacc[j][1] * rscale);
                *(float2*)(Ss + (r + 8) * S_LD + c) =
                    make_float2(sacc[j][2] * rscale, sacc[j][3] * rscale);
            }
        }
        __syncthreads();

        {
            int r = tid >> 2, seg = tid & 3;
            float* Sf = (float*)Ss;
            int nvalid = q0 + r - kt * 64 + 1;
            if (nvalid > 64) nvalid = 64;
            float m_old = mbuf[r], l_old = lbuf[r];
            int c0 = seg * 16;
            float pm = -1e30f;
#pragma unroll
            for (int c = 0; c < 16; c++) {
                int cc = c0 + c;
                float s = Sf[r * S_LD + cc];
                pm = (cc < nvalid) ? fmaxf(pm, s) : pm;
            }
            pm = fmaxf(pm, __shfl_xor_sync(0xffffffffu, pm, 1));
            pm = fmaxf(pm, __shfl_xor_sync(0xffffffffu, pm, 2));
            float m_new = fmaxf(m_old, pm);
            float alpha = fast_exp(m_old - m_new);
            float psum = 0.f;
#pragma unroll
            for (int c = 0; c < 16; c++) {
                int cc = c0 + c;
                float p = (cc < nvalid) ? fast_exp(Sf[r * S_LD + cc] - m_new) : 0.f;
                psum += p;
                Ss[r * S_LD + cc] = f2tf(p);
            }
            psum += __shfl_xor_sync(0xffffffffu, psum, 1);
            psum += __shfl_xor_sync(0xffffffffu, psum, 2);
            mbuf[r] = m_new;
            lbuf[r] = l_old * alpha + psum;
            abuf[r] = alpha;
        }
        __syncthreads();

        {
            int r = wm * 16 + lr;
            float al0 = abuf[r], al1 = abuf[r + 8];
#pragma unroll
            for (int j = 0; j < 4; j++) {
                accO[j][0] *= al0; accO[j][1] *= al0;
                accO[j][2] *= al1; accO[j][3] *= al1;
            }
#pragma unroll
            for (int ks = 0; ks < 8; ks++) {
                int c0 = ks * 8;
                uint32_t a0 = Ss[r * S_LD + c0 + lc];
                uint32_t a1 = Ss[(r + 8) * S_LD + c0 + lc];
                uint32_t a2 = Ss[r * S_LD + c0 + lc + 4];
                uint32_t a3 = Ss[(r + 8) * S_LD + c0 + lc + 4];
#pragma unroll
                for (int j = 0; j < 4; j++) {
                    int n = wn * 32 + j * 8 + lr;
                    uint32_t b0 = Vs[(c0 + lc) * V_LD + n];
                    uint32_t b1 = Vs[(c0 + lc + 4) * V_LD + n];
                    mma8(accO[j], a0, a1, a2, a3, b0, b1);
                }
            }
        }
        __syncthreads();
    }

    {
        int r = wm * 16 + lr;
        float il0 = 1.f / lbuf[r], il1 = 1.f / lbuf[r + 8];
#pragma unroll
        for (int j = 0; j < 4; j++) {
            int c = h * 64 + wn * 32 + j * 8 + lc * 2;
            size_t row0 = rowB + q0 + r;
            *(float2*)(Y + row0 * 1024 + c) =
                make_float2(accO[j][0] * il0, accO[j][1] * il0);
            *(float2*)(Y + (row0 + 8) * 1024 + c) =
                make_float2(accO[j][2] * il1, accO[j][3] * il1);
        }
    }
}

// ---------------------------------------------------------------------------
// Launcher
// ---------------------------------------------------------------------------
extern "C" void kernel_launch(void* const* d_in, const int* in_sizes, int n_in,
                              void* d_out, int out_size)
{
    const float* x     = (const float*)d_in[0];
    const float* W_DQ  = (const float*)d_in[1];
    const float* W_UQ  = (const float*)d_in[2];
    const float* W_DKV = (const float*)d_in[3];
    const float* W_UK  = (const float*)d_in[4];
    const float* W_UV  = (const float*)d_in[5];
    const float* W_QR  = (const float*)d_in[6];
    const float* W_KR  = (const float*)d_in[7];
    const float* W_O   = (const float*)d_in[8];
    float* out = (float*)d_out;

    float *cQ, *qC, *cKV, *kC, *v, *qR, *kR, *y, *rope;
    cudaGetSymbolAddress((void**)&cQ,  g_cQ);
    cudaGetSymbolAddress((void**)&qC,  g_qC);
    cudaGetSymbolAddress((void**)&cKV, g_cKV);
    cudaGetSymbolAddress((void**)&kC,  g_kC);
    cudaGetSymbolAddress((void**)&v,   g_v);
    cudaGetSymbolAddress((void**)&qR,  g_qR);
    cudaGetSymbolAddress((void**)&kR,  g_kR);
    cudaGetSymbolAddress((void**)&y,   g_y);
    cudaGetSymbolAddress((void**)&rope, g_rope);

    const int SMEM_ATTN = SMEM_ATTN_WORDS * 4;
    cudaFuncSetAttribute(attn_mma,
                         cudaFuncAttributeMaxDynamicSharedMemorySize, SMEM_ATTN);
    cudaFuncSetAttribute(gemm_tf32<false>,
                         cudaFuncAttributeMaxDynamicSharedMemorySize, GEMM_SMEM);
    cudaFuncSetAttribute(gemm_tf32<true>,
                         cudaFuncAttributeMaxDynamicSharedMemorySize, GEMM_SMEM);

    dim3 blk(256);

    rope_kernel<<<(TT * 16 + 255) / 256, 256>>>(rope);

    // 1. c_Q = x @ W_DQ            (8192 x 4096 x 1024)
    gemm_tf32<false><<<dim3(32, 64), blk, GEMM_SMEM>>>(x, W_DQ, cQ, rope, BT, 4096, 1024);
    // 2. q_C = c_Q @ W_UQ          (8192 x 1024 x 4096)
    gemm_tf32<false><<<dim3(8, 64), blk, GEMM_SMEM>>>(cQ, W_UQ, qC, rope, BT, 1024, 4096);
    // 3. c_KV = x @ W_DKV          (8192 x 256 x 1024)
    gemm_tf32<false><<<dim3(2, 64), blk, GEMM_SMEM>>>(x, W_DKV, cKV, rope, BT, 256, 1024);
    // 4. k_C = c_KV @ W_UK         (8192 x 1024 x 256)
    gemm_tf32<false><<<dim3(8, 64), blk, GEMM_SMEM>>>(cKV, W_UK, kC, rope, BT, 1024, 256);
    // 5. v = c_KV @ W_UV           (8192 x 1024 x 256)
    gemm_tf32<false><<<dim3(8, 64), blk, GEMM_SMEM>>>(cKV, W_UV, v, rope, BT, 1024, 256);
    // 6. q_R = (c_Q @ W_QR) * rope (8192 x 512 x 4096)
    gemm_tf32<true><<<dim3(4, 64), blk, GEMM_SMEM>>>(cQ, W_QR, qR, rope, BT, 512, 4096);
    // 7. k_R = (x @ W_KR) * rope   (8192 x 32 x 1024)
    kr_kernel<<<BT / 8, 256>>>(x, W_KR, rope, kR);
    // 8. attention -> y
    attn_mma<<<dim3(TT / 64, NHEAD, 4), blk, SMEM_ATTN>>>(qC, qR, kC, kR, v, y);
    // 9. out = y @ W_O             (8192 x 1024 x 1024)
    gemm_tf32<false><<<dim3(8, 64), blk, GEMM_SMEM>>>(y, W_O, out, rope, BT, 1024, 1024);
}

// round 6
// speedup vs baseline: 2.5197x; 1.1451x over previous
#include <cuda_runtime.h>
#include <math.h>
#include <stdint.h>

// ---------------------------------------------------------------------------
// MLA attention, tf32 tensor-core, fused GEMMs, 2-stage cp.async, K-tile 32.
// B=4, T=2048, C=1024, H=16, HS=64, DHR=32, head dim = 96.
// ---------------------------------------------------------------------------

#define BT    8192
#define TT    2048
#define NHEAD 16

// Scratch
__device__ float g_cQ [(size_t)BT * 4096];
__device__ float g_q  [(size_t)BT * 1536];   // [qC (1024) | qR (512)]
__device__ float g_cKV[(size_t)BT * 256];
__device__ float g_kv [(size_t)BT * 2048];   // [kC (1024) | v (1024)]
__device__ float g_kR [(size_t)BT * 32];
__device__ float g_y  [(size_t)BT * 1024];
__device__ float g_rope[TT * 16];

// ---------------------------------------------------------------------------
// Helpers
// ---------------------------------------------------------------------------
__device__ __forceinline__ uint32_t f2tf(float x) {
    uint32_t r;
    asm("cvt.rna.tf32.f32 %0, %1;" : "=r"(r) : "f"(x));
    return r;
}

__device__ __forceinline__ void mma8(float* c, uint32_t a0, uint32_t a1,
                                     uint32_t a2, uint32_t a3,
                                     uint32_t b0, uint32_t b1) {
    asm volatile(
        "mma.sync.aligned.m16n8k8.row.col.f32.tf32.tf32.f32 "
        "{%0,%1,%2,%3}, {%4,%5,%6,%7}, {%8,%9}, {%0,%1,%2,%3};"
        : "+f"(c[0]), "+f"(c[1]), "+f"(c[2]), "+f"(c[3])
        : "r"(a0), "r"(a1), "r"(a2), "r"(a3), "r"(b0), "r"(b1));
}

__device__ __forceinline__ void cp16(float* dst, const float* src) {
    uint32_t d = (uint32_t)__cvta_generic_to_shared(dst);
    asm volatile("cp.async.ca.shared.global [%0], [%1], 16;" :: "r"(d), "l"(src));
}
#define CP_COMMIT() asm volatile("cp.async.commit_group;")
#define CP_WAIT1()  asm volatile("cp.async.wait_group 1;")

// exp on the FMA pipe (exp2 split + deg-5 poly), rel err ~2e-6.
__device__ __forceinline__ float fast_exp(float x) {
    float y = fmaxf(x * 1.4426950408889634f, -126.0f);
    float z = y + 12582912.0f;
    int   n = __float_as_int(z) - 0x4B400000;
    float f = y - (z - 12582912.0f);
    float p = 1.33336498e-3f;
    p = fmaf(p, f, 9.61817697e-3f);
    p = fmaf(p, f, 5.55041087e-2f);
    p = fmaf(p, f, 2.40226510e-1f);
    p = fmaf(p, f, 6.93147181e-1f);
    p = fmaf(p, f, 1.0f);
    return __int_as_float(__float_as_int(p) + (n << 23));
}

// ---------------------------------------------------------------------------
// RoPE scale table
// ---------------------------------------------------------------------------
__global__ void rope_kernel(float* rope) {
    int idx = blockIdx.x * 256 + threadIdx.x;
    if (idx >= TT * 16) return;
    int t = idx >> 4, j = idx & 15;
    double inv = pow(10000.0, -(double)j / 16.0);
    float ph = (float)t * (float)inv;
    rope[idx] = cosf(ph) + sinf(ph);
}

// ---------------------------------------------------------------------------
// tf32 GEMM, K-tile 32, 2-stage cp.async. C[M,N] = A[M,K] @ [B1|B2][K,N].
// B columns [0,nsplit) come from B1 (row stride NB1), [nsplit,N) from B2
// (row stride NB2). Rope epilogue applied for out-columns >= ropeFrom.
// M%128==0, N%128==0, nsplit%128==0, K%32==0.
// CTA 128x128, 8 warps 4(M)x2(N), mma m16n8k8, ascending-k accumulation.
// ---------------------------------------------------------------------------
#define AS_LD  36
#define BS_LD  136
#define A_WORDS (128 * AS_LD)
#define B_WORDS (32 * BS_LD)
#define GEMM_SMEM (2 * (A_WORDS + B_WORDS) * 4)

__device__ __forceinline__ void gemm_load_tile(
    float* As, float* Bs, const float* Ap, const float* Bp,
    int k0, int K, int NB, int tid)
{
#pragma unroll
    for (int u = 0; u < 4; u++) {                // A: 128 x 32
        int idx = tid + 256 * u;                 // 0..1023 chunks of 4
        int r = idx >> 3, c = (idx & 7) << 2;
        cp16(&As[r * AS_LD + c], Ap + (size_t)r * K + k0 + c);
    }
#pragma unroll
    for (int u = 0; u < 4; u++) {                // B: 32 x 128
        int idx = tid + 256 * u;
        int r = idx >> 5, c = (idx & 31) << 2;
        cp16(&Bs[r * BS_LD + c], Bp + (size_t)(k0 + r) * NB + c);
    }
}

__global__ __launch_bounds__(256, 2)
void gemm_tf32(const float* __restrict__ A,
               const float* __restrict__ B1, const float* __restrict__ B2,
               float* __restrict__ C, const float* __restrict__ rope,
               int M, int N, int K, int nsplit, int NB1, int NB2, int ropeFrom)
{
    extern __shared__ float smf[];
    float* As = smf;                         // [2][A_WORDS]
    float* Bs = smf + 2 * A_WORDS;           // [2][B_WORDS]

    const int tid = threadIdx.x;
    const int warp = tid >> 5, lane = tid & 31;
    const int wm = warp >> 1, wn = warp & 1;
    const int lr = lane >> 2, lc = lane & 3;
    const int bx = blockIdx.x, by = blockIdx.y;

    float acc[2][8][4];
#pragma unroll
    for (int i = 0; i < 2; i++)
#pragma unroll
        for (int j = 0; j < 8; j++)
#pragma unroll
            for (int q = 0; q < 4; q++) acc[i][j][q] = 0.f;

    const float* Ap = A + (size_t)(by * 128) * K;
    const bool second = (bx * 128 >= nsplit);
    const float* Bp = second ? B2 + (bx * 128 - nsplit) : B1 + bx * 128;
    const int NB = second ? NB2 : NB1;

    const int ktiles = K >> 5;

    gemm_load_tile(As, Bs, Ap, Bp, 0, K, NB, tid);
    CP_COMMIT();

    for (int kt = 0; kt < ktiles; kt++) {
        int nk = kt + 1;
        if (nk < ktiles)
            gemm_load_tile(As + (nk & 1) * A_WORDS, Bs + (nk & 1) * B_WORDS,
                           Ap, Bp, nk << 5, K, NB, tid);
        CP_COMMIT();
        CP_WAIT1();
        __syncthreads();

        const float* As_ = As + (kt & 1) * A_WORDS;
        const float* Bs_ = Bs + (kt & 1) * B_WORDS;

#pragma unroll
        for (int ks = 0; ks < 4; ks++) {
            int kk = ks * 8;
            uint32_t af[2][4];
#pragma unroll
            for (int i = 0; i < 2; i++) {
                int r = wm * 32 + i * 16 + lr;
                af[i][0] = f2tf(As_[r * AS_LD + kk + lc]);
                af[i][1] = f2tf(As_[(r + 8) * AS_LD + kk + lc]);
                af[i][2] = f2tf(As_[r * AS_LD + kk + lc + 4]);
                af[i][3] = f2tf(As_[(r + 8) * AS_LD + kk + lc + 4]);
            }
#pragma unroll
            for (int j = 0; j < 8; j++) {
                int n = wn * 64 + j * 8 + lr;
                uint32_t b0 = f2tf(Bs_[(kk + lc) * BS_LD + n]);
                uint32_t b1 = f2tf(Bs_[(kk + lc + 4) * BS_LD + n]);
#pragma unroll
                for (int i = 0; i < 2; i++)
                    mma8(acc[i][j], af[i][0], af[i][1], af[i][2], af[i][3], b0, b1);
            }
        }
        __syncthreads();
    }

#pragma unroll
    for (int i = 0; i < 2; i++) {
        int r0 = by * 128 + wm * 32 + i * 16 + lr;
#pragma unroll
        for (int j = 0; j < 8; j++) {
            int c0 = bx * 128 + wn * 64 + j * 8 + lc * 2;
            if (c0 < ropeFrom) {
                *(float2*)(C + (size_t)r0 * N + c0)       = make_float2(acc[i][j][0], acc[i][j][1]);
                *(float2*)(C + (size_t)(r0 + 8) * N + c0) = make_float2(acc[i][j][2], acc[i][j][3]);
            } else {
                float s0 = rope[(r0 & (TT - 1)) * 16 + (c0 & 15)];
                float s1 = rope[(r0 & (TT - 1)) * 16 + ((c0 + 1) & 15)];
                float s2 = rope[((r0 + 8) & (TT - 1)) * 16 + (c0 & 15)];
                float s3 = rope[((r0 + 8) & (TT - 1)) * 16 + ((c0 + 1) & 15)];
                *(float2*)(C + (size_t)r0 * N + c0)       = make_float2(acc[i][j][0] * s0, acc[i][j][1] * s1);
                *(float2*)(C + (size_t)(r0 + 8) * N + c0) = make_float2(acc[i][j][2] * s2, acc[i][j][3] * s3);
            }
        }
    }
}

// ---------------------------------------------------------------------------
// k_R = (x @ W_KR) * rope   (8192 x 32, K=1024)
// ---------------------------------------------------------------------------
__global__ void kr_kernel(const float* __restrict__ x, const float* __restrict__ Wkr,
                          const float* __restrict__ rope, float* __restrict__ out)
{
    int m = blockIdx.x * 8 + (threadIdx.x >> 5);
    int n = threadIdx.x & 31;
    const float* xr = x + (size_t)m * 1024;
    float s = 0.f;
#pragma unroll 8
    for (int k = 0; k < 1024; k++) s += xr[k] * Wkr[k * 32 + n];
    out[(size_t)m * 32 + n] = s * rope[(m & (TT - 1)) * 16 + (n & 15)];
}

// ---------------------------------------------------------------------------
// Causal flash attention with tf32 mma. Packed q [BT,1536], kv [BT,2048].
// ---------------------------------------------------------------------------
#define Q_LD 100
#define K_LD 100
#define V_LD 72
#define S_LD 68
#define SMEM_ATTN_WORDS (64*Q_LD + 64*K_LD + 64*V_LD + 64*S_LD + 192)

__global__ __launch_bounds__(256, 2)
void attn_mma(const float* __restrict__ q, const float* __restrict__ kv,
              const float* __restrict__ kR, float* __restrict__ Y)
{
    extern __shared__ uint32_t sm[];
    uint32_t* Qs = sm;
    uint32_t* Ks = Qs + 64 * Q_LD;
    uint32_t* Vs = Ks + 64 * K_LD;
    uint32_t* Ss = Vs + 64 * V_LD;
    float* mbuf = (float*)(Ss + 64 * S_LD);
    float* lbuf = mbuf + 64;
    float* abuf = lbuf + 64;

    const int qt = blockIdx.x, h = blockIdx.y, b = blockIdx.z;
    const int tid = threadIdx.x, warp = tid >> 5, lane = tid & 31;
    const int lr = lane >> 2, lc = lane & 3;
    const int wm = warp & 3, wn = warp >> 2;
    const int q0 = qt * 64;
    const size_t rowB = (size_t)b * TT;

    for (int idx = tid; idx < 64 * 96; idx += 256) {
        int qr = idx / 96, d = idx - qr * 96;
        size_t row = rowB + q0 + qr;
        float v = (d < 64) ? q[row * 1536 + h * 64 + d]
                           : q[row * 1536 + 1024 + h * 32 + d - 64];
        Qs[qr * Q_LD + d] = f2tf(v);
    }
    if (tid < 64) { mbuf[tid] = -1e30f; lbuf[tid] = 0.f; }

    float accO[4][4];
#pragma unroll
    for (int j = 0; j < 4; j++)
#pragma unroll
        for (int qq = 0; qq < 4; qq++) accO[j][qq] = 0.f;

    const float rscale = 0.10206207261596575f;
    __syncthreads();

    for (int kt = 0; kt <= qt; kt++) {
        const size_t kr0 = rowB + kt * 64;
        for (int idx = tid; idx < 64 * 96; idx += 256) {
            int kc = idx / 96, d = idx - kc * 96;
            size_t row = kr0 + kc;
            float v = (d < 64) ? kv[row * 2048 + h * 64 + d]
                               : kR[row * 32 + d - 64];
            Ks[kc * K_LD + d] = f2tf(v);
        }
        for (int idx = tid; idx < 64 * 64; idx += 256) {
            int kc = idx >> 6, d = idx & 63;
            Vs[kc * V_LD + d] = f2tf(kv[(kr0 + kc) * 2048 + 1024 + h * 64 + d]);
        }
        __syncthreads();

        float sacc[4][4];
#pragma unroll
        for (int j = 0; j < 4; j++)
#pragma unroll
            for (int qq = 0; qq < 4; qq++) sacc[j][qq] = 0.f;

        {
            int r = wm * 16 + lr;
#pragma unroll
            for (int ks = 0; ks < 12; ks++) {
                int d0 = ks * 8;
                uint32_t a0 = Qs[r * Q_LD + d0 + lc];
                uint32_t a1 = Qs[(r + 8) * Q_LD + d0 + lc];
                uint32_t a2 = Qs[r * Q_LD + d0 + lc + 4];
                uint32_t a3 = Qs[(r + 8) * Q_LD + d0 + lc + 4];
#pragma unroll
                for (int j = 0; j < 4; j++) {
                    int n = wn * 32 + j * 8 + lr;
                    uint32_t b0 = Ks[n * K_LD + d0 + lc];
                    uint32_t b1 = Ks[n * K_LD + d0 + lc + 4];
                    mma8(sacc[j], a0, a1, a2, a3, b0, b1);
                }
            }
#pragma unroll
            for (int j = 0; j < 4; j++) {
                int c = wn * 32 + j * 8 + lc * 2;
                *(float2*)(Ss + r * S_LD + c) =
                    make_float2(sacc[j][0] * rscale, sacc[j][1] * rscale);
                *(float2*)(Ss + (r + 8) * S_LD + c) =
                    make_float2(sacc[j][2] * rscale, sacc[j][3] * rscale);
            }
        }
        __syncthreads();

        {
            int r = tid >> 2, seg = tid & 3;
            float* Sf = (float*)Ss;
            int nvalid = q0 + r - kt * 64 + 1;
            if (nvalid > 64) nvalid = 64;
            float m_old = mbuf[r], l_old = lbuf[r];
            int c0 = seg * 16;
            float pm = -1e30f;
#pragma unroll
            for (int c = 0; c < 16; c++) {
                int cc = c0 + c;
                float s = Sf[r * S_LD + cc];
                pm = (cc < nvalid) ? fmaxf(pm, s) : pm;
            }
            pm = fmaxf(pm, __shfl_xor_sync(0xffffffffu, pm, 1));
            pm = fmaxf(pm, __shfl_xor_sync(0xffffffffu, pm, 2));
            float m_new = fmaxf(m_old, pm);
            float alpha = fast_exp(m_old - m_new);
            float psum = 0.f;
#pragma unroll
            for (int c = 0; c < 16; c++) {
                int cc = c0 + c;
                float p = (cc < nvalid) ? fast_exp(Sf[r * S_LD + cc] - m_new) : 0.f;
                psum += p;
                Ss[r * S_LD + cc] = f2tf(p);
            }
            psum += __shfl_xor_sync(0xffffffffu, psum, 1);
            psum += __shfl_xor_sync(0xffffffffu, psum, 2);
            mbuf[r] = m_new;
            lbuf[r] = l_old * alpha + psum;
            abuf[r] = alpha;
        }
        __syncthreads();

        {
            int r = wm * 16 + lr;
            float al0 = abuf[r], al1 = abuf[r + 8];
#pragma unroll
            for (int j = 0; j < 4; j++) {
                accO[j][0] *= al0; accO[j][1] *= al0;
                accO[j][2] *= al1; accO[j][3] *= al1;
            }
#pragma unroll
            for (int ks = 0; ks < 8; ks++) {
                int c0 = ks * 8;
                uint32_t a0 = Ss[r * S_LD + c0 + lc];
                uint32_t a1 = Ss[(r + 8) * S_LD + c0 + lc];
                uint32_t a2 = Ss[r * S_LD + c0 + lc + 4];
                uint32_t a3 = Ss[(r + 8) * S_LD + c0 + lc + 4];
#pragma unroll
                for (int j = 0; j < 4; j++) {
                    int n = wn * 32 + j * 8 + lr;
                    uint32_t b0 = Vs[(c0 + lc) * V_LD + n];
                    uint32_t b1 = Vs[(c0 + lc + 4) * V_LD + n];
                    mma8(accO[j], a0, a1, a2, a3, b0, b1);
                }
            }
        }
        __syncthreads();
    }

    {
        int r = wm * 16 + lr;
        float il0 = 1.f / lbuf[r], il1 = 1.f / lbuf[r + 8];
#pragma unroll
        for (int j = 0; j < 4; j++) {
            int c = h * 64 + wn * 32 + j * 8 + lc * 2;
            size_t row0 = rowB + q0 + r;
            *(float2*)(Y + row0 * 1024 + c) =
                make_float2(accO[j][0] * il0, accO[j][1] * il0);
            *(float2*)(Y + (row0 + 8) * 1024 + c) =
                make_float2(accO[j][2] * il1, accO[j][3] * il1);
        }
    }
}

// ---------------------------------------------------------------------------
// Launcher
// ---------------------------------------------------------------------------
extern "C" void kernel_launch(void* const* d_in, const int* in_sizes, int n_in,
                              void* d_out, int out_size)
{
    const float* x     = (const float*)d_in[0];
    const float* W_DQ  = (const float*)d_in[1];
    const float* W_UQ  = (const float*)d_in[2];
    const float* W_DKV = (const float*)d_in[3];
    const float* W_UK  = (const float*)d_in[4];
    const float* W_UV  = (const float*)d_in[5];
    const float* W_QR  = (const float*)d_in[6];
    const float* W_KR  = (const float*)d_in[7];
    const float* W_O   = (const float*)d_in[8];
    float* out = (float*)d_out;

    float *cQ, *q, *cKV, *kv, *kR, *y, *rope;
    cudaGetSymbolAddress((void**)&cQ,  g_cQ);
    cudaGetSymbolAddress((void**)&q,   g_q);
    cudaGetSymbolAddress((void**)&cKV, g_cKV);
    cudaGetSymbolAddress((void**)&kv,  g_kv);
    cudaGetSymbolAddress((void**)&kR,  g_kR);
    cudaGetSymbolAddress((void**)&y,   g_y);
    cudaGetSymbolAddress((void**)&rope, g_rope);

    const int SMEM_ATTN = SMEM_ATTN_WORDS * 4;
    cudaFuncSetAttribute(attn_mma,
                         cudaFuncAttributeMaxDynamicSharedMemorySize, SMEM_ATTN);
    cudaFuncSetAttribute(gemm_tf32,
                         cudaFuncAttributeMaxDynamicSharedMemorySize, GEMM_SMEM);

    dim3 blk(256);
    const int NOROPE = 1 << 30;

    rope_kernel<<<(TT * 16 + 255) / 256, 256>>>(rope);

    // 1. c_Q = x @ W_DQ                  (8192 x 4096, K=1024)
    gemm_tf32<<<dim3(32, 64), blk, GEMM_SMEM>>>(x, W_DQ, W_DQ, cQ, rope,
                                                BT, 4096, 1024, NOROPE, 4096, 4096, NOROPE);
    // 2+6. q = c_Q @ [W_UQ | W_QR]       (8192 x 1536, K=4096), rope on cols>=1024
    gemm_tf32<<<dim3(12, 64), blk, GEMM_SMEM>>>(cQ, W_UQ, W_QR, q, rope,
                                                BT, 1536, 4096, 1024, 1024, 512, 1024);
    // 3. c_KV = x @ W_DKV                (8192 x 256, K=1024)
    gemm_tf32<<<dim3(2, 64), blk, GEMM_SMEM>>>(x, W_DKV, W_DKV, cKV, rope,
                                               BT, 256, 1024, NOROPE, 256, 256, NOROPE);
    // 4+5. kv = c_KV @ [W_UK | W_UV]     (8192 x 2048, K=256)
    gemm_tf32<<<dim3(16, 64), blk, GEMM_SMEM>>>(cKV, W_UK, W_UV, kv, rope,
                                                BT, 2048, 256, 1024, 1024, 1024, NOROPE);
    // 7. k_R = (x @ W_KR) * rope         (8192 x 32, K=1024)
    kr_kernel<<<BT / 8, 256>>>(x, W_KR, rope, kR);
    // 8. attention -> y
    attn_mma<<<dim3(TT / 64, NHEAD, 4), blk, SMEM_ATTN>>>(q, kv, kR, y);
    // 9. out = y @ W_O                   (8192 x 1024, K=1024)
    gemm_tf32<<<dim3(8, 64), blk, GEMM_SMEM>>>(y, W_O, W_O, out, rope,
                                               BT, 1024, 1024, NOROPE, 1024, 1024, NOROPE);
}

// round 7
// speedup vs baseline: 3.3175x; 1.3166x over previous
#include <cuda_runtime.h>
#include <math.h>
#include <stdint.h>

// ---------------------------------------------------------------------------
// MLA attention, tf32 tensor-core. Pre-rounded operands (no CVT in hot loops),
// fused GEMMs, 2-stage cp.async K-tile-32 GEMM, cp.async attention tiles.
// B=4, T=2048, C=1024, H=16, HS=64, DHR=32, head dim = 96.
// ---------------------------------------------------------------------------

#define BT    8192
#define TT    2048
#define NHEAD 16

// Scratch (intermediates; all stored pre-rounded to tf32 grid)
__device__ float g_cQ [(size_t)BT * 4096];
__device__ float g_q  [(size_t)BT * 1536];   // [qC (1024) | qR (512)]
__device__ float g_cKV[(size_t)BT * 256];
__device__ float g_kv [(size_t)BT * 2048];   // [kC (1024) | v (1024)]
__device__ float g_kR [(size_t)BT * 32];
__device__ float g_y  [(size_t)BT * 1024];
__device__ float g_rope[TT * 16];
// Pre-rounded copies of inputs feeding MMAs
__device__ float g_xt  [(size_t)BT * 1024];
__device__ float g_wdq [(size_t)1024 * 4096];
__device__ float g_wuq [(size_t)4096 * 1024];
__device__ float g_wdkv[(size_t)1024 * 256];
__device__ float g_wuk [(size_t)256 * 1024];
__device__ float g_wuv [(size_t)256 * 1024];
__device__ float g_wqr [(size_t)4096 * 512];
__device__ float g_wo  [(size_t)1024 * 1024];

// ---------------------------------------------------------------------------
// Helpers
// ---------------------------------------------------------------------------
__device__ __forceinline__ uint32_t f2tf(float x) {
    uint32_t r;
    asm("cvt.rna.tf32.f32 %0, %1;" : "=r"(r) : "f"(x));
    return r;
}
__device__ __forceinline__ float rnd(float x) { return __uint_as_float(f2tf(x)); }

__device__ __forceinline__ void mma8(float* c, uint32_t a0, uint32_t a1,
                                     uint32_t a2, uint32_t a3,
                                     uint32_t b0, uint32_t b1) {
    asm volatile(
        "mma.sync.aligned.m16n8k8.row.col.f32.tf32.tf32.f32 "
        "{%0,%1,%2,%3}, {%4,%5,%6,%7}, {%8,%9}, {%0,%1,%2,%3};"
        : "+f"(c[0]), "+f"(c[1]), "+f"(c[2]), "+f"(c[3])
        : "r"(a0), "r"(a1), "r"(a2), "r"(a3), "r"(b0), "r"(b1));
}

__device__ __forceinline__ void cp16(void* dst, const void* src) {
    uint32_t d = (uint32_t)__cvta_generic_to_shared(dst);
    asm volatile("cp.async.ca.shared.global [%0], [%1], 16;" :: "r"(d), "l"(src));
}
#define CP_COMMIT() asm volatile("cp.async.commit_group;")
#define CP_WAIT1()  asm volatile("cp.async.wait_group 1;")
#define CP_WAIT0()  asm volatile("cp.async.wait_group 0;")

// exp on the FMA pipe (exp2 split + deg-5 poly), rel err ~2e-6.
__device__ __forceinline__ float fast_exp(float x) {
    float y = fmaxf(x * 1.4426950408889634f, -126.0f);
    float z = y + 12582912.0f;
    int   n = __float_as_int(z) - 0x4B400000;
    float f = y - (z - 12582912.0f);
    float p = 1.33336498e-3f;
    p = fmaf(p, f, 9.61817697e-3f);
    p = fmaf(p, f, 5.55041087e-2f);
    p = fmaf(p, f, 2.40226510e-1f);
    p = fmaf(p, f, 6.93147181e-1f);
    p = fmaf(p, f, 1.0f);
    return __int_as_float(__float_as_int(p) + (n << 23));
}

// ---------------------------------------------------------------------------
// Pre-round inputs to the tf32 grid (values identical to consumer-side cvt).
// ---------------------------------------------------------------------------
__global__ void round_tf32_kernel(const float4* __restrict__ src,
                                  float4* __restrict__ dst, int n4)
{
    int i = blockIdx.x * 256 + threadIdx.x;
    if (i >= n4) return;
    float4 f = src[i];
    f.x = rnd(f.x); f.y = rnd(f.y); f.z = rnd(f.z); f.w = rnd(f.w);
    dst[i] = f;
}

// ---------------------------------------------------------------------------
// RoPE scale table
// ---------------------------------------------------------------------------
__global__ void rope_kernel(float* rope) {
    int idx = blockIdx.x * 256 + threadIdx.x;
    if (idx >= TT * 16) return;
    int t = idx >> 4, j = idx & 15;
    double inv = pow(10000.0, -(double)j / 16.0);
    float ph = (float)t * (float)inv;
    rope[idx] = cosf(ph) + sinf(ph);
}

// ---------------------------------------------------------------------------
// tf32 GEMM, K-tile 32, 2-stage cp.async. C[M,N] = A[M,K] @ [B1|B2][K,N].
// All operands pre-rounded to tf32 grid -> no CVT in the mainloop.
// roundOut: round C to tf32 grid on store (for tensors feeding later MMAs).
// ---------------------------------------------------------------------------
#define AS_LD  36
#define BS_LD  136
#define A_WORDS (128 * AS_LD)
#define B_WORDS (32 * BS_LD)
#define GEMM_SMEM (2 * (A_WORDS + B_WORDS) * 4)

__device__ __forceinline__ void gemm_load_tile(
    float* As, float* Bs, const float* Ap, const float* Bp,
    int k0, int K, int NB, int tid)
{
#pragma unroll
    for (int u = 0; u < 4; u++) {                // A: 128 x 32
        int idx = tid + 256 * u;
        int r = idx >> 3, c = (idx & 7) << 2;
        cp16(&As[r * AS_LD + c], Ap + (size_t)r * K + k0 + c);
    }
#pragma unroll
    for (int u = 0; u < 4; u++) {                // B: 32 x 128
        int idx = tid + 256 * u;
        int r = idx >> 5, c = (idx & 31) << 2;
        cp16(&Bs[r * BS_LD + c], Bp + (size_t)(k0 + r) * NB + c);
    }
}

__global__ __launch_bounds__(256, 2)
void gemm_tf32(const float* __restrict__ A,
               const float* __restrict__ B1, const float* __restrict__ B2,
               float* __restrict__ C, const float* __restrict__ rope,
               int M, int N, int K, int nsplit, int NB1, int NB2,
               int ropeFrom, int roundOut)
{
    extern __shared__ float smf[];
    float* As = smf;
    float* Bs = smf + 2 * A_WORDS;

    const int tid = threadIdx.x;
    const int warp = tid >> 5, lane = tid & 31;
    const int wm = warp >> 1, wn = warp & 1;
    const int lr = lane >> 2, lc = lane & 3;
    const int bx = blockIdx.x, by = blockIdx.y;

    float acc[2][8][4];
#pragma unroll
    for (int i = 0; i < 2; i++)
#pragma unroll
        for (int j = 0; j < 8; j++)
#pragma unroll
            for (int q = 0; q < 4; q++) acc[i][j][q] = 0.f;

    const float* Ap = A + (size_t)(by * 128) * K;
    const bool second = (bx * 128 >= nsplit);
    const float* Bp = second ? B2 + (bx * 128 - nsplit) : B1 + bx * 128;
    const int NB = second ? NB2 : NB1;

    const int ktiles = K >> 5;

    gemm_load_tile(As, Bs, Ap, Bp, 0, K, NB, tid);
    CP_COMMIT();

    for (int kt = 0; kt < ktiles; kt++) {
        int nk = kt + 1;
        if (nk < ktiles)
            gemm_load_tile(As + (nk & 1) * A_WORDS, Bs + (nk & 1) * B_WORDS,
                           Ap, Bp, nk << 5, K, NB, tid);
        CP_COMMIT();
        CP_WAIT1();
        __syncthreads();

        const float* As_ = As + (kt & 1) * A_WORDS;
        const float* Bs_ = Bs + (kt & 1) * B_WORDS;

#pragma unroll
        for (int ks = 0; ks < 4; ks++) {
            int kk = ks * 8;
            uint32_t af[2][4];
#pragma unroll
            for (int i = 0; i < 2; i++) {
                int r = wm * 32 + i * 16 + lr;
                af[i][0] = __float_as_uint(As_[r * AS_LD + kk + lc]);
                af[i][1] = __float_as_uint(As_[(r + 8) * AS_LD + kk + lc]);
                af[i][2] = __float_as_uint(As_[r * AS_LD + kk + lc + 4]);
                af[i][3] = __float_as_uint(As_[(r + 8) * AS_LD + kk + lc + 4]);
            }
#pragma unroll
            for (int j = 0; j < 8; j++) {
                int n = wn * 64 + j * 8 + lr;
                uint32_t b0 = __float_as_uint(Bs_[(kk + lc) * BS_LD + n]);
                uint32_t b1 = __float_as_uint(Bs_[(kk + lc + 4) * BS_LD + n]);
#pragma unroll
                for (int i = 0; i < 2; i++)
                    mma8(acc[i][j], af[i][0], af[i][1], af[i][2], af[i][3], b0, b1);
            }
        }
        __syncthreads();
    }

#pragma unroll
    for (int i = 0; i < 2; i++) {
        int r0 = by * 128 + wm * 32 + i * 16 + lr;
#pragma unroll
        for (int j = 0; j < 8; j++) {
            int c0 = bx * 128 + wn * 64 + j * 8 + lc * 2;
            float v0 = acc[i][j][0], v1 = acc[i][j][1];
            float v2 = acc[i][j][2], v3 = acc[i][j][3];
            if (c0 >= ropeFrom) {
                v0 *= rope[(r0 & (TT - 1)) * 16 + (c0 & 15)];
                v1 *= rope[(r0 & (TT - 1)) * 16 + ((c0 + 1) & 15)];
                v2 *= rope[((r0 + 8) & (TT - 1)) * 16 + (c0 & 15)];
                v3 *= rope[((r0 + 8) & (TT - 1)) * 16 + ((c0 + 1) & 15)];
            }
            if (roundOut) {
                v0 = rnd(v0); v1 = rnd(v1); v2 = rnd(v2); v3 = rnd(v3);
            }
            *(float2*)(C + (size_t)r0 * N + c0)       = make_float2(v0, v1);
            *(float2*)(C + (size_t)(r0 + 8) * N + c0) = make_float2(v2, v3);
        }
    }
}

// ---------------------------------------------------------------------------
// k_R = (x @ W_KR) * rope   (8192 x 32, K=1024); output rounded to tf32 grid.
// Uses ORIGINAL fp32 x (FFMA path, numerics unchanged from prior rounds).
// ---------------------------------------------------------------------------
__global__ void kr_kernel(const float* __restrict__ x, const float* __restrict__ Wkr,
                          const float* __restrict__ rope, float* __restrict__ out)
{
    int m = blockIdx.x * 8 + (threadIdx.x >> 5);
    int n = threadIdx.x & 31;
    const float* xr = x + (size_t)m * 1024;
    float s = 0.f;
#pragma unroll 8
    for (int k = 0; k < 1024; k++) s += xr[k] * Wkr[k * 32 + n];
    out[(size_t)m * 32 + n] = rnd(s * rope[(m & (TT - 1)) * 16 + (n & 15)]);
}

// ---------------------------------------------------------------------------
// Causal flash attention, tf32 mma, cp.async tile loads, no CVT on Q/K/V.
// Packed q [BT,1536], kv [BT,2048]. Output y rounded to tf32 grid.
// ---------------------------------------------------------------------------
#define Q_LD 100
#define K_LD 100
#define V_LD 72
#define S_LD 68
#define SMEM_ATTN_WORDS (64*Q_LD + 64*K_LD + 64*V_LD + 64*S_LD + 192)

__global__ __launch_bounds__(256, 2)
void attn_mma(const float* __restrict__ q, const float* __restrict__ kv,
              const float* __restrict__ kR, float* __restrict__ Y)
{
    extern __shared__ uint32_t sm[];
    uint32_t* Qs = sm;
    uint32_t* Ks = Qs + 64 * Q_LD;
    uint32_t* Vs = Ks + 64 * K_LD;
    uint32_t* Ss = Vs + 64 * V_LD;
    float* mbuf = (float*)(Ss + 64 * S_LD);
    float* lbuf = mbuf + 64;
    float* abuf = lbuf + 64;

    const int qt = blockIdx.x, h = blockIdx.y, b = blockIdx.z;
    const int tid = threadIdx.x, warp = tid >> 5, lane = tid & 31;
    const int lr = lane >> 2, lc = lane & 3;
    const int wm = warp & 3, wn = warp >> 2;
    const int q0 = qt * 64;
    const size_t rowB = (size_t)b * TT;

    // Q tile via cp.async: 64 rows x 24 16B-chunks (16 from qC, 8 from qR)
#pragma unroll
    for (int u = 0; u < 6; u++) {
        int idx = tid + 256 * u;          // 0..1535
        int qr = idx / 24, c = idx - qr * 24;
        size_t row = rowB + q0 + qr;
        const float* src = (c < 16) ? q + row * 1536 + h * 64 + c * 4
                                    : q + row * 1536 + 1024 + h * 32 + (c - 16) * 4;
        cp16(&Qs[qr * Q_LD + c * 4], src);
    }
    CP_COMMIT();
    if (tid < 64) { mbuf[tid] = -1e30f; lbuf[tid] = 0.f; }

    float accO[4][4];
#pragma unroll
    for (int j = 0; j < 4; j++)
#pragma unroll
        for (int qq = 0; qq < 4; qq++) accO[j][qq] = 0.f;

    const float rscale = 0.10206207261596575f;

    for (int kt = 0; kt <= qt; kt++) {
        const size_t kr0 = rowB + kt * 64;
        // K tile: 64 rows x 24 chunks (16 from kv kC-half, 8 from kR)
#pragma unroll
        for (int u = 0; u < 6; u++) {
            int idx = tid + 256 * u;
            int kc = idx / 24, c = idx - kc * 24;
            size_t row = kr0 + kc;
            const float* src = (c < 16) ? kv + row * 2048 + h * 64 + c * 4
                                        : kR + row * 32 + (c - 16) * 4;
            cp16(&Ks[kc * K_LD + c * 4], src);
        }
        // V tile: 64 rows x 16 chunks
#pragma unroll
        for (int u = 0; u < 4; u++) {
            int idx = tid + 256 * u;
            int kc = idx >> 4, c = idx & 15;
            cp16(&Vs[kc * V_LD + c * 4], kv + (kr0 + kc) * 2048 + 1024 + h * 64 + c * 4);
        }
        CP_COMMIT();
        CP_WAIT0();
        __syncthreads();

        float sacc[4][4];
#pragma unroll
        for (int j = 0; j < 4; j++)
#pragma unroll
            for (int qq = 0; qq < 4; qq++) sacc[j][qq] = 0.f;

        {
            int r = wm * 16 + lr;
#pragma unroll
            for (int ks = 0; ks < 12; ks++) {
                int d0 = ks * 8;
                uint32_t a0 = Qs[r * Q_LD + d0 + lc];
                uint32_t a1 = Qs[(r + 8) * Q_LD + d0 + lc];
                uint32_t a2 = Qs[r * Q_LD + d0 + lc + 4];
                uint32_t a3 = Qs[(r + 8) * Q_LD + d0 + lc + 4];
#pragma unroll
                for (int j = 0; j < 4; j++) {
                    int n = wn * 32 + j * 8 + lr;
                    uint32_t b0 = Ks[n * K_LD + d0 + lc];
                    uint32_t b1 = Ks[n * K_LD + d0 + lc + 4];
                    mma8(sacc[j], a0, a1, a2, a3, b0, b1);
                }
            }
#pragma unroll
            for (int j = 0; j < 4; j++) {
                int c = wn * 32 + j * 8 + lc * 2;
                *(float2*)(Ss + r * S_LD + c) =
                    make_float2(sacc[j][0] * rscale, sacc[j][1] * rscale);
                *(float2*)(Ss + (r + 8) * S_LD + c) =
                    make_float2(sacc[j][2] * rscale, sacc[j][3] * rscale);
            }
        }
        __syncthreads();

        {
            int r = tid >> 2, seg = tid & 3;
            float* Sf = (float*)Ss;
            int nvalid = q0 + r - kt * 64 + 1;
            if (nvalid > 64) nvalid = 64;
            float m_old = mbuf[r], l_old = lbuf[r];
            int c0 = seg * 16;
            float pm = -1e30f;
#pragma unroll
            for (int c = 0; c < 16; c++) {
                int cc = c0 + c;
                float s = Sf[r * S_LD + cc];
                pm = (cc < nvalid) ? fmaxf(pm, s) : pm;
            }
            pm = fmaxf(pm, __shfl_xor_sync(0xffffffffu, pm, 1));
            pm = fmaxf(pm, __shfl_xor_sync(0xffffffffu, pm, 2));
            float m_new = fmaxf(m_old, pm);
            float alpha = fast_exp(m_old - m_new);
            float psum = 0.f;
#pragma unroll
            for (int c = 0; c < 16; c++) {
                int cc = c0 + c;
                float p = (cc < nvalid) ? fast_exp(Sf[r * S_LD + cc] - m_new) : 0.f;
                psum += p;
                Ss[r * S_LD + cc] = f2tf(p);
            }
            psum += __shfl_xor_sync(0xffffffffu, psum, 1);
            psum += __shfl_xor_sync(0xffffffffu, psum, 2);
            mbuf[r] = m_new;
            lbuf[r] = l_old * alpha + psum;
            abuf[r] = alpha;
        }
        __syncthreads();

        {
            int r = wm * 16 + lr;
            float al0 = abuf[r], al1 = abuf[r + 8];
#pragma unroll
            for (int j = 0; j < 4; j++) {
                accO[j][0] *= al0; accO[j][1] *= al0;
                accO[j][2] *= al1; accO[j][3] *= al1;
            }
#pragma unroll
            for (int ks = 0; ks < 8; ks++) {
                int c0 = ks * 8;
                uint32_t a0 = Ss[r * S_LD + c0 + lc];
                uint32_t a1 = Ss[(r + 8) * S_LD + c0 + lc];
                uint32_t a2 = Ss[r * S_LD + c0 + lc + 4];
                uint32_t a3 = Ss[(r + 8) * S_LD + c0 + lc + 4];
#pragma unroll
                for (int j = 0; j < 4; j++) {
                    int n = wn * 32 + j * 8 + lr;
                    uint32_t b0 = Vs[(c0 + lc) * V_LD + n];
                    uint32_t b1 = Vs[(c0 + lc + 4) * V_LD + n];
                    mma8(accO[j], a0, a1, a2, a3, b0, b1);
                }
            }
        }
        __syncthreads();
    }

    {
        int r = wm * 16 + lr;
        float il0 = 1.f / lbuf[r], il1 = 1.f / lbuf[r + 8];
#pragma unroll
        for (int j = 0; j < 4; j++) {
            int c = h * 64 + wn * 32 + j * 8 + lc * 2;
            size_t row0 = rowB + q0 + r;
            *(float2*)(Y + row0 * 1024 + c) =
                make_float2(rnd(accO[j][0] * il0), rnd(accO[j][1] * il0));
            *(float2*)(Y + (row0 + 8) * 1024 + c) =
                make_float2(rnd(accO[j][2] * il1), rnd(accO[j][3] * il1));
        }
    }
}

// ---------------------------------------------------------------------------
// Launcher
// ---------------------------------------------------------------------------
static inline void round_to(const float* src, float* dst, size_t n) {
    int n4 = (int)(n >> 2);
    round_tf32_kernel<<<(n4 + 255) / 256, 256>>>((const float4*)src, (float4*)dst, n4);
}

extern "C" void kernel_launch(void* const* d_in, const int* in_sizes, int n_in,
                              void* d_out, int out_size)
{
    const float* x     = (const float*)d_in[0];
    const float* W_DQ  = (const float*)d_in[1];
    const float* W_UQ  = (const float*)d_in[2];
    const float* W_DKV = (const float*)d_in[3];
    const float* W_UK  = (const float*)d_in[4];
    const float* W_UV  = (const float*)d_in[5];
    const float* W_QR  = (const float*)d_in[6];
    const float* W_KR  = (const float*)d_in[7];
    const float* W_O   = (const float*)d_in[8];
    float* out = (float*)d_out;

    float *cQ, *q, *cKV, *kv, *kR, *y, *rope;
    float *xt, *wdq, *wuq, *wdkv, *wuk, *wuv, *wqr, *wo;
    cudaGetSymbolAddress((void**)&cQ,  g_cQ);
    cudaGetSymbolAddress((void**)&q,   g_q);
    cudaGetSymbolAddress((void**)&cKV, g_cKV);
    cudaGetSymbolAddress((void**)&kv,  g_kv);
    cudaGetSymbolAddress((void**)&kR,  g_kR);
    cudaGetSymbolAddress((void**)&y,   g_y);
    cudaGetSymbolAddress((void**)&rope, g_rope);
    cudaGetSymbolAddress((void**)&xt,   g_xt);
    cudaGetSymbolAddress((void**)&wdq,  g_wdq);
    cudaGetSymbolAddress((void**)&wuq,  g_wuq);
    cudaGetSymbolAddress((void**)&wdkv, g_wdkv);
    cudaGetSymbolAddress((void**)&wuk,  g_wuk);
    cudaGetSymbolAddress((void**)&wuv,  g_wuv);
    cudaGetSymbolAddress((void**)&wqr,  g_wqr);
    cudaGetSymbolAddress((void**)&wo,   g_wo);

    const int SMEM_ATTN = SMEM_ATTN_WORDS * 4;
    cudaFuncSetAttribute(attn_mma,
                         cudaFuncAttributeMaxDynamicSharedMemorySize, SMEM_ATTN);
    cudaFuncSetAttribute(gemm_tf32,
                         cudaFuncAttributeMaxDynamicSharedMemorySize, GEMM_SMEM);

    dim3 blk(256);
    const int NOROPE = 1 << 30;

    rope_kernel<<<(TT * 16 + 255) / 256, 256>>>(rope);

    // Pre-round inputs to the tf32 grid.
    round_to(x,     xt,   (size_t)BT * 1024);
    round_to(W_DQ,  wdq,  (size_t)1024 * 4096);
    round_to(W_UQ,  wuq,  (size_t)4096 * 1024);
    round_to(W_DKV, wdkv, (size_t)1024 * 256);
    round_to(W_UK,  wuk,  (size_t)256 * 1024);
    round_to(W_UV,  wuv,  (size_t)256 * 1024);
    round_to(W_QR,  wqr,  (size_t)4096 * 512);
    round_to(W_O,   wo,   (size_t)1024 * 1024);

    // 1. c_Q = x @ W_DQ                  (8192 x 4096, K=1024), round out
    gemm_tf32<<<dim3(32, 64), blk, GEMM_SMEM>>>(xt, wdq, wdq, cQ, rope,
                                                BT, 4096, 1024, NOROPE, 4096, 4096, NOROPE, 1);
    // 2+6. q = c_Q @ [W_UQ | W_QR]       (8192 x 1536, K=4096), rope cols>=1024, round out
    gemm_tf32<<<dim3(12, 64), blk, GEMM_SMEM>>>(cQ, wuq, wqr, q, rope,
                                                BT, 1536, 4096, 1024, 1024, 512, 1024, 1);
    // 3. c_KV = x @ W_DKV                (8192 x 256, K=1024), round out
    gemm_tf32<<<dim3(2, 64), blk, GEMM_SMEM>>>(xt, wdkv, wdkv, cKV, rope,
                                               BT, 256, 1024, NOROPE, 256, 256, NOROPE, 1);
    // 4+5. kv = c_KV @ [W_UK | W_UV]     (8192 x 2048, K=256), round out
    gemm_tf32<<<dim3(16, 64), blk, GEMM_SMEM>>>(cKV, wuk, wuv, kv, rope,
                                                BT, 2048, 256, 1024, 1024, 1024, NOROPE, 1);
    // 7. k_R = (x @ W_KR) * rope         (8192 x 32, K=1024), round out
    kr_kernel<<<BT / 8, 256>>>(x, W_KR, rope, kR);
    // 8. attention -> y (rounded)
    attn_mma<<<dim3(TT / 64, NHEAD, 4), blk, SMEM_ATTN>>>(q, kv, kR, y);
    // 9. out = y @ W_O                   (8192 x 1024, K=1024), final: no rounding
    gemm_tf32<<<dim3(8, 64), blk, GEMM_SMEM>>>(y, wo, wo, out, rope,
                                               BT, 1024, 1024, NOROPE, 1024, 1024, NOROPE, 0);
}

// round 10
// speedup vs baseline: 3.5127x; 1.0589x over previous
#include <cuda_runtime.h>
#include <math.h>
#include <stdint.h>

// ---------------------------------------------------------------------------
// MLA attention, tf32 tensor-core. Pre-rounded + transposed weights,
// ldmatrix fragment loads, fused GEMMs, 2-stage cp.async K-tile-32 GEMM.
// B=4, T=2048, C=1024, H=16, HS=64, DHR=32, head dim = 96.
// ---------------------------------------------------------------------------

#define BT    8192
#define TT    2048
#define NHEAD 16

// Scratch (intermediates; all stored pre-rounded to tf32 grid)
__device__ float g_cQ [(size_t)BT * 4096];
__device__ float g_q  [(size_t)BT * 1536];   // [qC (1024) | qR (512)]
__device__ float g_cKV[(size_t)BT * 256];
__device__ float g_kv [(size_t)BT * 2048];   // [kC (1024) | v (1024)]
__device__ float g_kR [(size_t)BT * 32];
__device__ float g_y  [(size_t)BT * 1024];
__device__ float g_rope[TT * 16];
// Pre-rounded x; pre-rounded TRANSPOSED weights (n-major: W^T[n][k])
__device__ float g_xt  [(size_t)BT * 1024];
__device__ float g_wdq [(size_t)4096 * 1024];
__device__ float g_wuq [(size_t)1024 * 4096];
__device__ float g_wdkv[(size_t)256 * 1024];
__device__ float g_wuk [(size_t)1024 * 256];
__device__ float g_wuv [(size_t)1024 * 256];
__device__ float g_wqr [(size_t)512 * 4096];
__device__ float g_wo  [(size_t)1024 * 1024];

// ---------------------------------------------------------------------------
// Helpers
// ---------------------------------------------------------------------------
__device__ __forceinline__ uint32_t f2tf(float x) {
    uint32_t r;
    asm("cvt.rna.tf32.f32 %0, %1;" : "=r"(r) : "f"(x));
    return r;
}
__device__ __forceinline__ float rnd(float x) { return __uint_as_float(f2tf(x)); }

__device__ __forceinline__ void mma8(float* c, uint32_t a0, uint32_t a1,
                                     uint32_t a2, uint32_t a3,
                                     uint32_t b0, uint32_t b1) {
    asm volatile(
        "mma.sync.aligned.m16n8k8.row.col.f32.tf32.tf32.f32 "
        "{%0,%1,%2,%3}, {%4,%5,%6,%7}, {%8,%9}, {%0,%1,%2,%3};"
        : "+f"(c[0]), "+f"(c[1]), "+f"(c[2]), "+f"(c[3])
        : "r"(a0), "r"(a1), "r"(a2), "r"(a3), "r"(b0), "r"(b1));
}

__device__ __forceinline__ void ldsm4(uint32_t& r0, uint32_t& r1,
                                      uint32_t& r2, uint32_t& r3, uint32_t addr) {
    asm volatile("ldmatrix.sync.aligned.m8n8.x4.shared.b16 {%0,%1,%2,%3}, [%4];"
                 : "=r"(r0), "=r"(r1), "=r"(r2), "=r"(r3) : "r"(addr));
}

__device__ __forceinline__ void cp16(void* dst, const void* src) {
    uint32_t d = (uint32_t)__cvta_generic_to_shared(dst);
    asm volatile("cp.async.ca.shared.global [%0], [%1], 16;" :: "r"(d), "l"(src));
}
#define CP_COMMIT() asm volatile("cp.async.commit_group;")
#define CP_WAIT1()  asm volatile("cp.async.wait_group 1;")
#define CP_WAIT0()  asm volatile("cp.async.wait_group 0;")

// exp on the FMA pipe (exp2 split + deg-5 poly), rel err ~2e-6.
__device__ __forceinline__ float fast_exp(float x) {
    float y = fmaxf(x * 1.4426950408889634f, -126.0f);
    float z = y + 12582912.0f;
    int   n = __float_as_int(z) - 0x4B400000;
    float f = y - (z - 12582912.0f);
    float p = 1.33336498e-3f;
    p = fmaf(p, f, 9.61817697e-3f);
    p = fmaf(p, f, 5.55041087e-2f);
    p = fmaf(p, f, 2.40226510e-1f);
    p = fmaf(p, f, 6.93147181e-1f);
    p = fmaf(p, f, 1.0f);
    return __int_as_float(__float_as_int(p) + (n << 23));
}

// ---------------------------------------------------------------------------
// Pre-round x (plain) and weights (round + transpose to n-major).
// ---------------------------------------------------------------------------
__global__ void round_tf32_kernel(const float4* __restrict__ src,
                                  float4* __restrict__ dst, int n4)
{
    int i = blockIdx.x * 256 + threadIdx.x;
    if (i >= n4) return;
    float4 f = src[i];
    f.x = rnd(f.x); f.y = rnd(f.y); f.z = rnd(f.z); f.w = rnd(f.w);
    dst[i] = f;
}

// src[K][N] -> dst[N][K] (rounded). K,N multiples of 32. 256 threads.
__global__ void round_transpose_kernel(const float* __restrict__ src,
                                       float* __restrict__ dst, int K, int N)
{
    __shared__ float tile[32][33];
    int n0 = blockIdx.x * 32, k0 = blockIdx.y * 32;
    int tx = threadIdx.x & 31, ty = threadIdx.x >> 5;   // ty 0..7
#pragma unroll
    for (int i = ty; i < 32; i += 8)
        tile[i][tx] = src[(size_t)(k0 + i) * N + n0 + tx];
    __syncthreads();
#pragma unroll
    for (int i = ty; i < 32; i += 8)
        dst[(size_t)(n0 + i) * K + k0 + tx] = rnd(tile[tx][i]);
}

// ---------------------------------------------------------------------------
// RoPE scale table
// ---------------------------------------------------------------------------
__global__ void rope_kernel(float* rope) {
    int idx = blockIdx.x * 256 + threadIdx.x;
    if (idx >= TT * 16) return;
    int t = idx >> 4, j = idx & 15;
    double inv = pow(10000.0, -(double)j / 16.0);
    float ph = (float)t * (float)inv;
    rope[idx] = cosf(ph) + sinf(ph);
}

// ---------------------------------------------------------------------------
// tf32 GEMM, K-tile 32, 2-stage cp.async, ldmatrix fragments.
// C[M,N] = A[M,K] @ B, with B given TRANSPOSED: Bt[n][k] (row stride K).
// Columns [0,nsplit) from B1t, [nsplit,N) from B2t. Rope epilogue >= ropeFrom.
// ---------------------------------------------------------------------------
#define AS_LD  36
#define BS_LD  36
#define A_WORDS (128 * AS_LD)
#define B_WORDS (128 * BS_LD)
#define GEMM_SMEM (2 * (A_WORDS + B_WORDS) * 4)

__device__ __forceinline__ void gemm_load_tile(
    float* As, float* Bs, const float* Ap, const float* Bp,
    int k0, int K, int tid)
{
#pragma unroll
    for (int u = 0; u < 4; u++) {                // A: 128 rows x 32 k
        int idx = tid + 256 * u;
        int r = idx >> 3, c = (idx & 7) << 2;
        cp16(&As[r * AS_LD + c], Ap + (size_t)r * K + k0 + c);
    }
#pragma unroll
    for (int u = 0; u < 4; u++) {                // Bt: 128 n-rows x 32 k
        int idx = tid + 256 * u;
        int r = idx >> 3, c = (idx & 7) << 2;
        cp16(&Bs[r * BS_LD + c], Bp + (size_t)r * K + k0 + c);
    }
}

__global__ __launch_bounds__(256, 2)
void gemm_tf32(const float* __restrict__ A,
               const float* __restrict__ B1t, const float* __restrict__ B2t,
               float* __restrict__ C, const float* __restrict__ rope,
               int M, int N, int K, int nsplit, int ropeFrom, int roundOut)
{
    extern __shared__ float smf[];
    float* As = smf;
    float* Bs = smf + 2 * A_WORDS;

    const int tid = threadIdx.x;
    const int warp = tid >> 5, lane = tid & 31;
    const int wm = warp >> 1, wn = warp & 1;
    const int lr = lane >> 2, lc = lane & 3;
    const int g = lane >> 3, tin = lane & 7;
    const int bx = blockIdx.x, by = blockIdx.y;

    float acc[2][8][4];
#pragma unroll
    for (int i = 0; i < 2; i++)
#pragma unroll
        for (int j = 0; j < 8; j++)
#pragma unroll
            for (int q = 0; q < 4; q++) acc[i][j][q] = 0.f;

    const float* Ap = A + (size_t)(by * 128) * K;
    const bool second = (bx * 128 >= nsplit);
    const float* Bp = second ? B2t + (size_t)(bx * 128 - nsplit) * K
                             : B1t + (size_t)(bx * 128) * K;

    // Per-thread ldmatrix offsets (floats, relative to stage base):
    const int aoff = (wm * 32 + (g & 1) * 8 + tin) * AS_LD + (g >> 1) * 4;
    const int boff = (wn * 64 + (g >> 1) * 8 + tin) * BS_LD + (g & 1) * 4;
    const uint32_t as_u = (uint32_t)__cvta_generic_to_shared(As);
    const uint32_t bs_u = (uint32_t)__cvta_generic_to_shared(Bs);

    const int ktiles = K >> 5;

    gemm_load_tile(As, Bs, Ap, Bp, 0, K, tid);
    CP_COMMIT();

    for (int kt = 0; kt < ktiles; kt++) {
        int nk = kt + 1;
        if (nk < ktiles)
            gemm_load_tile(As + (nk & 1) * A_WORDS, Bs + (nk & 1) * B_WORDS,
                           Ap, Bp, nk << 5, K, tid);
        CP_COMMIT();
        CP_WAIT1();
        __syncthreads();

        uint32_t aS = as_u + (uint32_t)(((kt & 1) * A_WORDS + aoff) * 4);
        uint32_t bS = bs_u + (uint32_t)(((kt & 1) * B_WORDS + boff) * 4);

#pragma unroll
        for (int ks = 0; ks < 4; ks++) {
            int kk = ks * 8;
            uint32_t a[2][4];
            ldsm4(a[0][0], a[0][1], a[0][2], a[0][3], aS + kk * 4);
            ldsm4(a[1][0], a[1][1], a[1][2], a[1][3], aS + (16 * AS_LD + kk) * 4);
#pragma unroll
            for (int jj = 0; jj < 4; jj++) {
                uint32_t b0, b1, b2, b3;
                ldsm4(b0, b1, b2, b3, bS + (jj * 16 * BS_LD + kk) * 4);
                mma8(acc[0][2 * jj],     a[0][0], a[0][1], a[0][2], a[0][3], b0, b1);
                mma8(acc[1][2 * jj],     a[1][0], a[1][1], a[1][2], a[1][3], b0, b1);
                mma8(acc[0][2 * jj + 1], a[0][0], a[0][1], a[0][2], a[0][3], b2, b3);
                mma8(acc[1][2 * jj + 1], a[1][0], a[1][1], a[1][2], a[1][3], b2, b3);
            }
        }
        __syncthreads();
    }

#pragma unroll
    for (int i = 0; i < 2; i++) {
        int r0 = by * 128 + wm * 32 + i * 16 + lr;
#pragma unroll
        for (int j = 0; j < 8; j++) {
            int c0 = bx * 128 + wn * 64 + j * 8 + lc * 2;
            float v0 = acc[i][j][0], v1 = acc[i][j][1];
            float v2 = acc[i][j][2], v3 = acc[i][j][3];
            if (c0 >= ropeFrom) {
                v0 *= rope[(r0 & (TT - 1)) * 16 + (c0 & 15)];
                v1 *= rope[(r0 & (TT - 1)) * 16 + ((c0 + 1) & 15)];
                v2 *= rope[((r0 + 8) & (TT - 1)) * 16 + (c0 & 15)];
                v3 *= rope[((r0 + 8) & (TT - 1)) * 16 + ((c0 + 1) & 15)];
            }
            if (roundOut) {
                v0 = rnd(v0); v1 = rnd(v1); v2 = rnd(v2); v3 = rnd(v3);
            }
            *(float2*)(C + (size_t)r0 * N + c0)       = make_float2(v0, v1);
            *(float2*)(C + (size_t)(r0 + 8) * N + c0) = make_float2(v2, v3);
        }
    }
}

// ---------------------------------------------------------------------------
// k_R = (x @ W_KR) * rope   (8192 x 32, K=1024); original fp32 x (FFMA path).
// ---------------------------------------------------------------------------
__global__ void kr_kernel(const float* __restrict__ x, const float* __restrict__ Wkr,
                          const float* __restrict__ rope, float* __restrict__ out)
{
    int m = blockIdx.x * 8 + (threadIdx.x >> 5);
    int n = threadIdx.x & 31;
    const float* xr = x + (size_t)m * 1024;
    float s = 0.f;
#pragma unroll 8
    for (int k = 0; k < 1024; k++) s += xr[k] * Wkr[k * 32 + n];
    out[(size_t)m * 32 + n] = rnd(s * rope[(m & (TT - 1)) * 16 + (n & 15)]);
}

// ---------------------------------------------------------------------------
// Causal flash attention, tf32 mma, cp.async tile loads (unchanged from R7).
// ---------------------------------------------------------------------------
#define Q_LD 100
#define K_LD 100
#define V_LD 72
#define S_LD 68
#define SMEM_ATTN_WORDS (64*Q_LD + 64*K_LD + 64*V_LD + 64*S_LD + 192)

__global__ __launch_bounds__(256, 2)
void attn_mma(const float* __restrict__ q, const float* __restrict__ kv,
              const float* __restrict__ kR, float* __restrict__ Y)
{
    extern __shared__ uint32_t sm[];
    uint32_t* Qs = sm;
    uint32_t* Ks = Qs + 64 * Q_LD;
    uint32_t* Vs = Ks + 64 * K_LD;
    uint32_t* Ss = Vs + 64 * V_LD;
    float* mbuf = (float*)(Ss + 64 * S_LD);
    float* lbuf = mbuf + 64;
    float* abuf = lbuf + 64;

    const int qt = blockIdx.x, h = blockIdx.y, b = blockIdx.z;
    const int tid = threadIdx.x, warp = tid >> 5, lane = tid & 31;
    const int lr = lane >> 2, lc = lane & 3;
    const int wm = warp & 3, wn = warp >> 2;
    const int q0 = qt * 64;
    const size_t rowB = (size_t)b * TT;

#pragma unroll
    for (int u = 0; u < 6; u++) {
        int idx = tid + 256 * u;
        int qr = idx / 24, c = idx - qr * 24;
        size_t row = rowB + q0 + qr;
        const float* src = (c < 16) ? q + row * 1536 + h * 64 + c * 4
                                    : q + row * 1536 + 1024 + h * 32 + (c - 16) * 4;
        cp16(&Qs[qr * Q_LD + c * 4], src);
    }
    CP_COMMIT();
    if (tid < 64) { mbuf[tid] = -1e30f; lbuf[tid] = 0.f; }

    float accO[4][4];
#pragma unroll
    for (int j = 0; j < 4; j++)
#pragma unroll
        for (int qq = 0; qq < 4; qq++) accO[j][qq] = 0.f;

    const float rscale = 0.10206207261596575f;

    for (int kt = 0; kt <= qt; kt++) {
        const size_t kr0 = rowB + kt * 64;
#pragma unroll
        for (int u = 0; u < 6; u++) {
            int idx = tid + 256 * u;
            int kc = idx / 24, c = idx - kc * 24;
            size_t row = kr0 + kc;
            const float* src = (c < 16) ? kv + row * 2048 + h * 64 + c * 4
                                        : kR + row * 32 + (c - 16) * 4;
            cp16(&Ks[kc * K_LD + c * 4], src);
        }
#pragma unroll
        for (int u = 0; u < 4; u++) {
            int idx = tid + 256 * u;
            int kc = idx >> 4, c = idx & 15;
            cp16(&Vs[kc * V_LD + c * 4], kv + (kr0 + kc) * 2048 + 1024 + h * 64 + c * 4);
        }
        CP_COMMIT();
        CP_WAIT0();
        __syncthreads();

        float sacc[4][4];
#pragma unroll
        for (int j = 0; j < 4; j++)
#pragma unroll
            for (int qq = 0; qq < 4; qq++) sacc[j][qq] = 0.f;

        {
            int r = wm * 16 + lr;
#pragma unroll
            for (int ks = 0; ks < 12; ks++) {
                int d0 = ks * 8;
                uint32_t a0 = Qs[r * Q_LD + d0 + lc];
                uint32_t a1 = Qs[(r + 8) * Q_LD + d0 + lc];
                uint32_t a2 = Qs[r * Q_LD + d0 + lc + 4];
                uint32_t a3 = Qs[(r + 8) * Q_LD + d0 + lc + 4];
#pragma unroll
                for (int j = 0; j < 4; j++) {
                    int n = wn * 32 + j * 8 + lr;
                    uint32_t b0 = Ks[n * K_LD + d0 + lc];
                    uint32_t b1 = Ks[n * K_LD + d0 + lc + 4];
                    mma8(sacc[j], a0, a1, a2, a3, b0, b1);
                }
            }
#pragma unroll
            for (int j = 0; j < 4; j++) {
                int c = wn * 32 + j * 8 + lc * 2;
                *(float2*)(Ss + r * S_LD + c) =
                    make_float2(sacc[j][0] * rscale, sacc[j][1] * rscale);
                *(float2*)(Ss + (r + 8) * S_LD + c) =
                    make_float2(sacc[j][2] * rscale, sacc[j][3] * rscale);
            }
        }
        __syncthreads();

        {
            int r = tid >> 2, seg = tid & 3;
            float* Sf = (float*)Ss;
            int nvalid = q0 + r - kt * 64 + 1;
            if (nvalid > 64) nvalid = 64;
            float m_old = mbuf[r], l_old = lbuf[r];
            int c0 = seg * 16;
            float pm = -1e30f;
#pragma unroll
            for (int c = 0; c < 16; c++) {
                int cc = c0 + c;
                float s = Sf[r * S_LD + cc];
                pm = (cc < nvalid) ? fmaxf(pm, s) : pm;
            }
            pm = fmaxf(pm, __shfl_xor_sync(0xffffffffu, pm, 1));
            pm = fmaxf(pm, __shfl_xor_sync(0xffffffffu, pm, 2));
            float m_new = fmaxf(m_old, pm);
            float alpha = fast_exp(m_old - m_new);
            float psum = 0.f;
#pragma unroll
            for (int c = 0; c < 16; c++) {
                int cc = c0 + c;
                float p = (cc < nvalid) ? fast_exp(Sf[r * S_LD + cc] - m_new) : 0.f;
                psum += p;
                Ss[r * S_LD + cc] = f2tf(p);
            }
            psum += __shfl_xor_sync(0xffffffffu, psum, 1);
            psum += __shfl_xor_sync(0xffffffffu, psum, 2);
            mbuf[r] = m_new;
            lbuf[r] = l_old * alpha + psum;
            abuf[r] = alpha;
        }
        __syncthreads();

        {
            int r = wm * 16 + lr;
            float al0 = abuf[r], al1 = abuf[r + 8];
#pragma unroll
            for (int j = 0; j < 4; j++) {
                accO[j][0] *= al0; accO[j][1] *= al0;
                accO[j][2] *= al1; accO[j][3] *= al1;
            }
#pragma unroll
            for (int ks = 0; ks < 8; ks++) {
                int c0 = ks * 8;
                uint32_t a0 = Ss[r * S_LD + c0 + lc];
                uint32_t a1 = Ss[(r + 8) * S_LD + c0 + lc];
                uint32_t a2 = Ss[r * S_LD + c0 + lc + 4];
                uint32_t a3 = Ss[(r + 8) * S_LD + c0 + lc + 4];
#pragma unroll
                for (int j = 0; j < 4; j++) {
                    int n = wn * 32 + j * 8 + lr;
                    uint32_t b0 = Vs[(c0 + lc) * V_LD + n];
                    uint32_t b1 = Vs[(c0 + lc + 4) * V_LD + n];
                    mma8(accO[j], a0, a1, a2, a3, b0, b1);
                }
            }
        }
        __syncthreads();
    }

    {
        int r = wm * 16 + lr;
        float il0 = 1.f / lbuf[r], il1 = 1.f / lbuf[r + 8];
#pragma unroll
        for (int j = 0; j < 4; j++) {
            int c = h * 64 + wn * 32 + j * 8 + lc * 2;
            size_t row0 = rowB + q0 + r;
            *(float2*)(Y + row0 * 1024 + c) =
                make_float2(rnd(accO[j][0] * il0), rnd(accO[j][1] * il0));
            *(float2*)(Y + (row0 + 8) * 1024 + c) =
                make_float2(rnd(accO[j][2] * il1), rnd(accO[j][3] * il1));
        }
    }
}

// ---------------------------------------------------------------------------
// Launcher
// ---------------------------------------------------------------------------
static inline void round_to(const float* src, float* dst, size_t n) {
    int n4 = (int)(n >> 2);
    round_tf32_kernel<<<(n4 + 255) / 256, 256>>>((const float4*)src, (float4*)dst, n4);
}
static inline void round_transpose(const float* src, float* dst, int K, int N) {
    round_transpose_kernel<<<dim3(N / 32, K / 32), 256>>>(src, dst, K, N);
}

extern "C" void kernel_launch(void* const* d_in, const int* in_sizes, int n_in,
                              void* d_out, int out_size)
{
    const float* x     = (const float*)d_in[0];
    const float* W_DQ  = (const float*)d_in[1];
    const float* W_UQ  = (const float*)d_in[2];
    const float* W_DKV = (const float*)d_in[3];
    const float* W_UK  = (const float*)d_in[4];
    const float* W_UV  = (const float*)d_in[5];
    const float* W_QR  = (const float*)d_in[6];
    const float* W_KR  = (const float*)d_in[7];
    const float* W_O   = (const float*)d_in[8];
    float* out = (float*)d_out;

    float *cQ, *q, *cKV, *kv, *kR, *y, *rope;
    float *xt, *wdq, *wuq, *wdkv, *wuk, *wuv, *wqr, *wo;
    cudaGetSymbolAddress((void**)&cQ,  g_cQ);
    cudaGetSymbolAddress((void**)&q,   g_q);
    cudaGetSymbolAddress((void**)&cKV, g_cKV);
    cudaGetSymbolAddress((void**)&kv,  g_kv);
    cudaGetSymbolAddress((void**)&kR,  g_kR);
    cudaGetSymbolAddress((void**)&y,   g_y);
    cudaGetSymbolAddress((void**)&rope, g_rope);
    cudaGetSymbolAddress((void**)&xt,   g_xt);
    cudaGetSymbolAddress((void**)&wdq,  g_wdq);
    cudaGetSymbolAddress((void**)&wuq,  g_wuq);
    cudaGetSymbolAddress((void**)&wdkv, g_wdkv);
    cudaGetSymbolAddress((void**)&wuk,  g_wuk);
    cudaGetSymbolAddress((void**)&wuv,  g_wuv);
    cudaGetSymbolAddress((void**)&wqr,  g_wqr);
    cudaGetSymbolAddress((void**)&wo,   g_wo);

    const int SMEM_ATTN = SMEM_ATTN_WORDS * 4;
    cudaFuncSetAttribute(attn_mma,
                         cudaFuncAttributeMaxDynamicSharedMemorySize, SMEM_ATTN);
    cudaFuncSetAttribute(gemm_tf32,
                         cudaFuncAttributeMaxDynamicSharedMemorySize, GEMM_SMEM);

    dim3 blk(256);
    const int NOROPE = 1 << 30;

    rope_kernel<<<(TT * 16 + 255) / 256, 256>>>(rope);

    // Pre-round x; round+transpose weights to n-major.
    round_to(x, xt, (size_t)BT * 1024);
    round_transpose(W_DQ,  wdq,  1024, 4096);   // -> [4096][1024]
    round_transpose(W_UQ,  wuq,  4096, 1024);   // -> [1024][4096]
    round_transpose(W_DKV, wdkv, 1024, 256);    // -> [256][1024]
    round_transpose(W_UK,  wuk,  256, 1024);    // -> [1024][256]
    round_transpose(W_UV,  wuv,  256, 1024);    // -> [1024][256]
    round_transpose(W_QR,  wqr,  4096, 512);    // -> [512][4096]
    round_transpose(W_O,   wo,   1024, 1024);   // -> [1024][1024]

    // 1. c_Q = x @ W_DQ                  (8192 x 4096, K=1024), round out
    gemm_tf32<<<dim3(32, 64), blk, GEMM_SMEM>>>(xt, wdq, wdq, cQ, rope,
                                                BT, 4096, 1024, NOROPE, NOROPE, 1);
    // 2+6. q = c_Q @ [W_UQ | W_QR]       (8192 x 1536, K=4096), rope cols>=1024
    gemm_tf32<<<dim3(12, 64), blk, GEMM_SMEM>>>(cQ, wuq, wqr, q, rope,
                                                BT, 1536, 4096, 1024, 1024, 1);
    // 3. c_KV = x @ W_DKV                (8192 x 256, K=1024), round out
    gemm_tf32<<<dim3(2, 64), blk, GEMM_SMEM>>>(xt, wdkv, wdkv, cKV, rope,
                                               BT, 256, 1024, NOROPE, NOROPE, 1);
    // 4+5. kv = c_KV @ [W_UK | W_UV]     (8192 x 2048, K=256), round out
    gemm_tf32<<<dim3(16, 64), blk, GEMM_SMEM>>>(cKV, wuk, wuv, kv, rope,
                                                BT, 2048, 256, 1024, NOROPE, 1);
    // 7. k_R = (x @ W_KR) * rope         (8192 x 32, K=1024), round out
    kr_kernel<<<BT / 8, 256>>>(x, W_KR, rope, kR);
    // 8. attention -> y (rounded)
    attn_mma<<<dim3(TT / 64, NHEAD, 4), blk, SMEM_ATTN>>>(q, kv, kR, y);
    // 9. out = y @ W_O                   (8192 x 1024, K=1024), final: no rounding
    gemm_tf32<<<dim3(8, 64), blk, GEMM_SMEM>>>(y, wo, wo, out, rope,
                                               BT, 1024, 1024, NOROPE, NOROPE, 0);
}